// round 10
// baseline (speedup 1.0000x reference)
#include <cuda_runtime.h>
#include <cuda_bf16.h>
#include <math.h>
#include <stdint.h>

// ---------------- Problem constants ----------------
#define BATCH   4
#define SEQ     2048
#define ROWS    (BATCH*SEQ)      // 8192
#define DIMS    1024
#define STATE   2048             // 2*DIMS
#define NTOT    (4*STATE)        // 8192 columns of GEMM1 output [K|u|gin|gout]
#define TCH     128              // scan chunk length
#define NCH     (SEQ/TCH)        // 16 chunks

// ---------------- Scratch (device globals; no allocation allowed) ----------------
__device__ __nv_bfloat16 g_xn[(size_t)ROWS*DIMS];       // 16MB  normalized input (bf16)
__device__ __nv_bfloat16 g_WT[(size_t)NTOT*DIMS];       // 16MB  [Wk|Wugg]^T as [n,k] bf16
__device__ __nv_bfloat16 g_WoutT[(size_t)DIMS*STATE];   // 4MB   Wout^T as [n,k] bf16
__device__ float g_C[(size_t)ROWS*NTOT];                // 256MB GEMM1 out (sig(K)|u|sig(gin)|sig(gout))
__device__ __nv_bfloat16 g_out1[(size_t)ROWS*STATE];    // 32MB  h*sigmoid(g_out) bf16
__device__ float g_chA[BATCH*NCH*STATE];
__device__ float g_chB[BATCH*NCH*STATE];
__device__ int   g_flags[BATCH*NCH];

// ---------------- Helpers ----------------
__device__ __forceinline__ uint32_t smem_u32(const void* p) {
    uint32_t a;
    asm("{ .reg .u64 t; cvta.to.shared.u64 t, %1; cvt.u32.u64 %0, t; }" : "=r"(a) : "l"(p));
    return a;
}
__device__ __forceinline__ void cp16(uint32_t dst, const void* src) {
    asm volatile("cp.async.cg.shared.global [%0], [%1], 16;" :: "r"(dst), "l"(src) : "memory");
}
#define CP_COMMIT() asm volatile("cp.async.commit_group;" ::: "memory")

__device__ __forceinline__ void ldm_x4(uint32_t* r, uint32_t addr) {
    asm volatile("ldmatrix.sync.aligned.m8n8.x4.shared.b16 {%0,%1,%2,%3}, [%4];"
                 : "=r"(r[0]), "=r"(r[1]), "=r"(r[2]), "=r"(r[3]) : "r"(addr));
}
__device__ __forceinline__ void mma_bf16(float* c, const uint32_t* a,
                                         uint32_t b0, uint32_t b1) {
    asm volatile(
        "mma.sync.aligned.m16n8k16.row.col.f32.bf16.bf16.f32 "
        "{%0,%1,%2,%3},{%4,%5,%6,%7},{%8,%9},{%0,%1,%2,%3};"
        : "+f"(c[0]), "+f"(c[1]), "+f"(c[2]), "+f"(c[3])
        : "r"(a[0]), "r"(a[1]), "r"(a[2]), "r"(a[3]), "r"(b0), "r"(b1));
}
// Fast sigmoid: MUFU.EX2-based exp + MUFU.RCP division (~4 SASS ops).
__device__ __forceinline__ float sigm(float v) {
    return __fdividef(1.0f, 1.0f + __expf(-v));
}

// ---------------- RMS split norm -> bf16 ----------------
__global__ void rmsnorm_kernel(const float* __restrict__ x,
                               const float* __restrict__ ls,
                               const float* __restrict__ rs,
                               const float* __restrict__ ss,
                               __nv_bfloat16* __restrict__ xn) {
    __shared__ float wsum[8];
    int row = blockIdx.x;
    int tid = threadIdx.x;                 // 256 threads, 4 elems each
    const float* xr = x + (size_t)row * DIMS;
    float4 xv = ((const float4*)xr)[tid];
    float s = xv.x*xv.x + xv.y*xv.y + xv.z*xv.z + xv.w*xv.w;
    #pragma unroll
    for (int o = 16; o; o >>= 1) s += __shfl_xor_sync(0xffffffffu, s, o);
    if ((tid & 31) == 0) wsum[tid >> 5] = s;
    __syncthreads();
    int half = tid >> 7;
    float tot = wsum[half*4+0] + wsum[half*4+1] + wsum[half*4+2] + wsum[half*4+3];
    float n = sqrtf(tot) * 0.04419417382415922f + 1e-8f;   // 1/sqrt(512)
    float inv = 1.0f / n;
    const float* sc = half ? rs : ls;
    int jb = (tid*4) & 511;
    float4 scv = ((const float4*)sc)[jb >> 2];
    float4 ssv = ((const float4*)ss)[tid];
    __nv_bfloat162 p0 = __floats2bfloat162_rn(xv.x * scv.x * inv * ssv.x,
                                              xv.y * scv.y * inv * ssv.y);
    __nv_bfloat162 p1 = __floats2bfloat162_rn(xv.z * scv.z * inv * ssv.z,
                                              xv.w * scv.w * inv * ssv.w);
    __nv_bfloat162* dst = (__nv_bfloat162*)(xn + (size_t)row * DIMS);
    dst[tid*2]   = p0;
    dst[tid*2+1] = p1;
}

// ---------------- Fused weight-prep: transpose Wk + Wugg into g_WT (one launch) ----------------
__global__ void prep_WT(const float* __restrict__ Wk, const float* __restrict__ Wugg,
                        __nv_bfloat16* __restrict__ dst) {
    __shared__ float tile[32][33];
    int z = blockIdx.z;
    const float* src = (z == 0) ? Wk : (Wugg + (z - 1) * 2048);
    int srcLD = (z == 0) ? 2048 : 6144;
    size_t dstBase = (size_t)z * 2048 * 1024;
    int r0 = blockIdx.y * 32, c0 = blockIdx.x * 32;
    int tx = threadIdx.x, ty = threadIdx.y;   // 32 x 8
    #pragma unroll
    for (int i = 0; i < 32; i += 8)
        tile[ty+i][tx] = src[(size_t)(r0+ty+i)*srcLD + c0 + tx];
    __syncthreads();
    #pragma unroll
    for (int i = 0; i < 32; i += 8)
        dst[dstBase + (size_t)(c0+ty+i)*1024 + r0 + tx] = __float2bfloat16_rn(tile[tx][ty+i]);
}

// ---------------- Plain transpose fp32 -> bf16 (Wout) ----------------
__global__ void transpose_bf16(const float* __restrict__ src, __nv_bfloat16* __restrict__ dst,
                               int R, int C) {
    __shared__ float tile[32][33];
    int r0 = blockIdx.y * 32, c0 = blockIdx.x * 32;
    int tx = threadIdx.x, ty = threadIdx.y;   // 32 x 8
    #pragma unroll
    for (int i = 0; i < 32; i += 8)
        tile[ty+i][tx] = src[(size_t)(r0+ty+i)*C + c0 + tx];
    __syncthreads();
    #pragma unroll
    for (int i = 0; i < 32; i += 8)
        dst[(size_t)(c0+ty+i)*R + r0 + tx] = __float2bfloat16_rn(tile[tx][ty+i]);
}

// ---------------- Legacy-MMA bf16 GEMM (R9 version, measured fast — unchanged) ----------------
#define BK 64
#define NST 3
#define AST (128*BK*2)         // 16384 bytes per A stage
#define BST (128*BK*2)         // 16384 bytes per B stage
#define GEMM_SMEM (NST*(AST+BST))   // 98304 = 96KB

__global__ void __launch_bounds__(256, 2)
gemm_bf16(const __nv_bfloat16* __restrict__ A, const __nv_bfloat16* __restrict__ B,
          float* __restrict__ C, int N, int K, int NIT,
          int mode, const float* __restrict__ resid) {
    extern __shared__ char smraw[];
    const uint32_t sbase = smem_u32(smraw);

    const int tid  = threadIdx.x;
    const int wid  = tid >> 5;
    const int lane = tid & 31;
    const int m0 = blockIdx.y * 128;
    const int n0 = blockIdx.x * 128;
    const int wm0 = (wid >> 2) * 64;      // warp row origin (0/64)
    const int wn0 = (wid & 3) * 32;       // warp col origin (0/32/64/96)
    const int blk = lane >> 3;            // 0..3
    const int lr8 = lane & 7;
    const int kb2 = (blk >> 1) * 16;      // +16B for k8..15 half

    // Hoisted fill addressing
    uint32_t sOff[4];
    const __nv_bfloat16 *gA[4], *gB[4];
    {
        int r = tid >> 3, c = tid & 7;
        #pragma unroll
        for (int i = 0; i < 4; i++) {
            int rr = r + i * 32;
            sOff[i] = (uint32_t)(rr * 128 + ((c ^ (rr & 7)) << 4));
            gA[i] = A + (size_t)(m0 + rr) * K + c * 8;
            gB[i] = B + (size_t)(n0 + rr) * K + c * 8;
        }
    }

    uint32_t offA[4], xrA[4], offB[2], xrB[2];
    #pragma unroll
    for (int mt = 0; mt < 4; mt++) {
        int r = wm0 + mt*16 + (blk & 1)*8 + lr8;
        offA[mt] = (uint32_t)r * 128u;
        xrA[mt]  = (uint32_t)(r & 7) << 4;
    }
    #pragma unroll
    for (int np = 0; np < 2; np++) {
        int r = wn0 + np*16 + (blk & 1)*8 + lr8;
        offB[np] = (uint32_t)r * 128u;
        xrB[np]  = (uint32_t)(r & 7) << 4;
    }

    float c[4][4][4];
    #pragma unroll
    for (int i = 0; i < 4; i++)
        #pragma unroll
        for (int j = 0; j < 4; j++)
            #pragma unroll
            for (int e = 0; e < 4; e++) c[i][j][e] = 0.0f;

    // Prologue: fill all 3 stages
    #pragma unroll
    for (int pf = 0; pf < NST; ++pf) {
        const uint32_t aS = sbase + pf*(AST+BST);
        const uint32_t bS = aS + AST;
        const int k0 = pf * BK;
        #pragma unroll
        for (int i = 0; i < 4; i++) cp16(aS + sOff[i], gA[i] + k0);
        #pragma unroll
        for (int i = 0; i < 4; i++) cp16(bS + sOff[i], gB[i] + k0);
        CP_COMMIT();
    }

    for (int it = 0; it < NIT; ++it) {
        const int s = it % NST;
        const uint32_t aS = sbase + s*(AST+BST);
        const uint32_t bS = aS + AST;

        int rem = NIT - 1 - it;
        if (rem >= 2)      asm volatile("cp.async.wait_group 2;" ::: "memory");
        else if (rem == 1) asm volatile("cp.async.wait_group 1;" ::: "memory");
        else               asm volatile("cp.async.wait_group 0;" ::: "memory");
        __syncthreads();

        #pragma unroll
        for (int kk = 0; kk < 4; ++kk) {
            uint32_t a[4][4], b[2][4];
            const uint32_t kbase = (uint32_t)(kk*32) + kb2;
            #pragma unroll
            for (int mt = 0; mt < 4; mt++)
                ldm_x4(a[mt], aS + offA[mt] + (kbase ^ xrA[mt]));
            #pragma unroll
            for (int np = 0; np < 2; np++)
                ldm_x4(b[np], bS + offB[np] + (kbase ^ xrB[np]));
            #pragma unroll
            for (int mt = 0; mt < 4; mt++)
                #pragma unroll
                for (int nt = 0; nt < 4; nt++) {
                    int np = nt >> 1, odd = nt & 1;
                    mma_bf16(c[mt][nt], a[mt], b[np][odd], b[np][2 + odd]);
                }
        }
        __syncthreads();   // everyone done reading stage s

        if (it + 3 < NIT) {
            const int k0 = (it + 3) * BK;
            #pragma unroll
            for (int i = 0; i < 4; i++) cp16(aS + sOff[i], gA[i] + k0);
            #pragma unroll
            for (int i = 0; i < 4; i++) cp16(bS + sOff[i], gB[i] + k0);
            CP_COMMIT();
        }
    }

    // Epilogue: direct float2 stores
    const int g = lane >> 2, tig = lane & 3;
    #pragma unroll
    for (int mt = 0; mt < 4; mt++) {
        int row = m0 + wm0 + mt*16 + g;
        #pragma unroll
        for (int nt = 0; nt < 4; nt++) {
            int col = n0 + wn0 + nt*8 + 2*tig;
            float v0 = c[mt][nt][0], v1 = c[mt][nt][1];
            float v2 = c[mt][nt][2], v3 = c[mt][nt][3];
            if (mode == 0) {
                bool sg = (col < 2048) || (col >= 4096);
                if (sg) { v0 = sigm(v0); v1 = sigm(v1); v2 = sigm(v2); v3 = sigm(v3); }
            } else {
                v0 += resid[(size_t)row * N + col];
                v1 += resid[(size_t)row * N + col + 1];
                v2 += resid[(size_t)(row+8) * N + col];
                v3 += resid[(size_t)(row+8) * N + col + 1];
            }
            *(float2*)(C + (size_t)row * N + col)     = make_float2(v0, v1);
            *(float2*)(C + (size_t)(row+8) * N + col) = make_float2(v2, v3);
        }
    }
}

// ---------------- Fused single-pass scan (decoupled look-back) ----------------
// Block = (256 channels) x (chunk ch) x (batch b). Pass 1 computes chunk summary,
// publishes + flag; look-back folds predecessor summaries; pass 2 replays chunk
// (C re-read hits L2) and writes gated output. Arithmetic identical to the old
// 3-phase version.
__global__ void __launch_bounds__(256)
scan_fused(const float* __restrict__ C,
           float* __restrict__ chA, float* __restrict__ chB,
           volatile int* __restrict__ flags,
           __nv_bfloat16* __restrict__ out1) {
    int cidx  = blockIdx.x * blockDim.x + threadIdx.x;   // 0..2047
    int ch    = blockIdx.y;
    int b     = blockIdx.z;
    int tid   = threadIdx.x;
    size_t base = (size_t)b * SEQ * NTOT;
    int t0 = ch * TCH;

    // ---- pass 1: chunk summary ----
    float Aacc = 1.0f, Bacc = 0.0f;
    float k0save = (t0 == 0) ? 1.0f : C[base + (size_t)(t0-1) * NTOT + cidx];
    float kprev = k0save;
    for (int tl = 0; tl < TCH; tl++) {
        int t = t0 + tl;
        size_t r = base + (size_t)t * NTOT;
        float Kc = C[r + cidx];
        float u  = C[r + 2048 + cidx];
        float gi = C[r + 4096 + cidx];
        float a  = (t == 0) ? 1.0f : kprev;
        kprev = Kc;
        float up = u * gi * (1.0f - Kc);
        Aacc = a * Aacc;
        Bacc = a * Bacc + up;
    }
    int sidx = (b * NCH + ch) * STATE + cidx;
    chA[sidx] = Aacc;
    chB[sidx] = Bacc;
    __threadfence();
    __syncthreads();
    if (tid == 0) flags[b * NCH + ch] = 1;

    // ---- look-back over predecessor chunks ----
    float hin = 0.0f, prodA = 1.0f;
    for (int p = ch - 1; p >= 0; --p) {
        if (tid == 0) {
            while (flags[b * NCH + p] == 0) { }
        }
        __syncthreads();
        __threadfence();   // acquire: order chA/chB reads after flag observation
        int pidx = (b * NCH + p) * STATE + cidx;
        hin   += prodA * chB[pidx];
        prodA *= chA[pidx];
    }

    // ---- pass 2: replay with true inflow (C re-read served by L2) ----
    float h = hin;
    kprev = k0save;
    for (int tl = 0; tl < TCH; tl++) {
        int t = t0 + tl;
        size_t r = base + (size_t)t * NTOT;
        float Kc = C[r + cidx];
        float u  = C[r + 2048 + cidx];
        float gi = C[r + 4096 + cidx];
        float go = C[r + 6144 + cidx];
        float a  = (t == 0) ? 1.0f : kprev;
        kprev = Kc;
        float up = u * gi * (1.0f - Kc);
        h = a * h + up;
        out1[((size_t)b * SEQ + t) * STATE + cidx] = __float2bfloat16_rn(h * go);
    }
}

// ---------------- Launch ----------------
extern "C" void kernel_launch(void* const* d_in, const int* in_sizes, int n_in,
                              void* d_out, int out_size) {
    const float* x    = (const float*)d_in[0];
    const float* ls   = (const float*)d_in[1];
    const float* rs   = (const float*)d_in[2];
    const float* ss   = (const float*)d_in[3];
    const float* Wk   = (const float*)d_in[4];
    const float* Wugg = (const float*)d_in[5];
    const float* Wout = (const float*)d_in[6];
    float* y = (float*)d_out;

    __nv_bfloat16 *p_xn, *p_WT, *p_WoutT, *p_out1;
    float *p_C, *p_chA, *p_chB;
    int *p_flags;
    cudaGetSymbolAddress((void**)&p_xn,    g_xn);
    cudaGetSymbolAddress((void**)&p_WT,    g_WT);
    cudaGetSymbolAddress((void**)&p_WoutT, g_WoutT);
    cudaGetSymbolAddress((void**)&p_C,     g_C);
    cudaGetSymbolAddress((void**)&p_out1,  g_out1);
    cudaGetSymbolAddress((void**)&p_chA,   g_chA);
    cudaGetSymbolAddress((void**)&p_chB,   g_chB);
    cudaGetSymbolAddress((void**)&p_flags, g_flags);

    cudaFuncSetAttribute(gemm_bf16, cudaFuncAttributeMaxDynamicSharedMemorySize, GEMM_SMEM);

    dim3 blk(32, 8);

    rmsnorm_kernel<<<ROWS, 256>>>(x, ls, rs, ss, p_xn);
    prep_WT<<<dim3(2048/32, 1024/32, 4), blk>>>(Wk, Wugg, p_WT);
    transpose_bf16<<<dim3(1024/32, 2048/32), blk>>>(Wout, p_WoutT, 2048, 1024);
    // global launch index 5 -> ncu profiles GEMM1
    gemm_bf16<<<dim3(NTOT/128, ROWS/128), 256, GEMM_SMEM>>>(p_xn, p_WT, p_C,
                                                            NTOT, DIMS, DIMS/BK, 0, nullptr);

    // reset look-back flags, then fused scan
    cudaMemsetAsync(p_flags, 0, BATCH * NCH * sizeof(int));
    scan_fused<<<dim3(STATE/256, NCH, BATCH), 256>>>(p_C, p_chA, p_chB, p_flags, p_out1);

    gemm_bf16<<<dim3(DIMS/128, ROWS/128), 256, GEMM_SMEM>>>(p_out1, p_WoutT, y,
                                                            DIMS, STATE, STATE/BK, 1, x);
}

// round 11
// speedup vs baseline: 1.0684x; 1.0684x over previous
#include <cuda_runtime.h>
#include <cuda_bf16.h>
#include <math.h>
#include <stdint.h>

// ---------------- Problem constants ----------------
#define BATCH   4
#define SEQ     2048
#define ROWS    (BATCH*SEQ)      // 8192
#define DIMS    1024
#define STATE   2048             // 2*DIMS
#define NTOT    (4*STATE)        // 8192 columns of GEMM1 output [K|u|gin|gout]
#define TCH     128              // scan chunk length
#define NCH     (SEQ/TCH)        // 16 chunks

// ---------------- Scratch (device globals; no allocation allowed) ----------------
__device__ __nv_bfloat16 g_xn[(size_t)ROWS*DIMS];       // 16MB  normalized input (bf16)
__device__ __nv_bfloat16 g_WT[(size_t)NTOT*DIMS];       // 16MB  [Wk|Wugg]^T as [n,k] bf16
__device__ __nv_bfloat16 g_WoutT[(size_t)DIMS*STATE];   // 4MB   Wout^T as [n,k] bf16
__device__ float g_C[(size_t)ROWS*NTOT];                // 256MB GEMM1 out (sig(K)|u|sig(gin)|sig(gout))
__device__ __nv_bfloat16 g_out1[(size_t)ROWS*STATE];    // 32MB  h*sigmoid(g_out) bf16
__device__ float g_chA[BATCH*NCH*STATE];
__device__ float g_chB[BATCH*NCH*STATE];
__device__ float g_hin[BATCH*NCH*STATE];

// ---------------- Helpers ----------------
__device__ __forceinline__ uint32_t smem_u32(const void* p) {
    uint32_t a;
    asm("{ .reg .u64 t; cvta.to.shared.u64 t, %1; cvt.u32.u64 %0, t; }" : "=r"(a) : "l"(p));
    return a;
}
__device__ __forceinline__ void cp16(uint32_t dst, const void* src) {
    asm volatile("cp.async.cg.shared.global [%0], [%1], 16;" :: "r"(dst), "l"(src) : "memory");
}
#define CP_COMMIT() asm volatile("cp.async.commit_group;" ::: "memory")

__device__ __forceinline__ void ldm_x4(uint32_t* r, uint32_t addr) {
    asm volatile("ldmatrix.sync.aligned.m8n8.x4.shared.b16 {%0,%1,%2,%3}, [%4];"
                 : "=r"(r[0]), "=r"(r[1]), "=r"(r[2]), "=r"(r[3]) : "r"(addr));
}
__device__ __forceinline__ void mma_bf16(float* c, const uint32_t* a,
                                         uint32_t b0, uint32_t b1) {
    asm volatile(
        "mma.sync.aligned.m16n8k16.row.col.f32.bf16.bf16.f32 "
        "{%0,%1,%2,%3},{%4,%5,%6,%7},{%8,%9},{%0,%1,%2,%3};"
        : "+f"(c[0]), "+f"(c[1]), "+f"(c[2]), "+f"(c[3])
        : "r"(a[0]), "r"(a[1]), "r"(a[2]), "r"(a[3]), "r"(b0), "r"(b1));
}
// Fast sigmoid: MUFU.EX2-based exp + MUFU.RCP division (~4 SASS ops).
__device__ __forceinline__ float sigm(float v) {
    return __fdividef(1.0f, 1.0f + __expf(-v));
}

// ---------------- RMS split norm -> bf16 ----------------
__global__ void rmsnorm_kernel(const float* __restrict__ x,
                               const float* __restrict__ ls,
                               const float* __restrict__ rs,
                               const float* __restrict__ ss,
                               __nv_bfloat16* __restrict__ xn) {
    __shared__ float wsum[8];
    int row = blockIdx.x;
    int tid = threadIdx.x;                 // 256 threads, 4 elems each
    const float* xr = x + (size_t)row * DIMS;
    float4 xv = ((const float4*)xr)[tid];
    float s = xv.x*xv.x + xv.y*xv.y + xv.z*xv.z + xv.w*xv.w;
    #pragma unroll
    for (int o = 16; o; o >>= 1) s += __shfl_xor_sync(0xffffffffu, s, o);
    if ((tid & 31) == 0) wsum[tid >> 5] = s;
    __syncthreads();
    int half = tid >> 7;
    float tot = wsum[half*4+0] + wsum[half*4+1] + wsum[half*4+2] + wsum[half*4+3];
    float n = sqrtf(tot) * 0.04419417382415922f + 1e-8f;   // 1/sqrt(512)
    float inv = 1.0f / n;
    const float* sc = half ? rs : ls;
    int jb = (tid*4) & 511;
    float4 scv = ((const float4*)sc)[jb >> 2];
    float4 ssv = ((const float4*)ss)[tid];
    __nv_bfloat162 p0 = __floats2bfloat162_rn(xv.x * scv.x * inv * ssv.x,
                                              xv.y * scv.y * inv * ssv.y);
    __nv_bfloat162 p1 = __floats2bfloat162_rn(xv.z * scv.z * inv * ssv.z,
                                              xv.w * scv.w * inv * ssv.w);
    __nv_bfloat162* dst = (__nv_bfloat162*)(xn + (size_t)row * DIMS);
    dst[tid*2]   = p0;
    dst[tid*2+1] = p1;
}

// ---------------- Fused weight-prep: transpose Wk + Wugg into g_WT (one launch) ----------------
__global__ void prep_WT(const float* __restrict__ Wk, const float* __restrict__ Wugg,
                        __nv_bfloat16* __restrict__ dst) {
    __shared__ float tile[32][33];
    int z = blockIdx.z;
    const float* src = (z == 0) ? Wk : (Wugg + (z - 1) * 2048);
    int srcLD = (z == 0) ? 2048 : 6144;
    size_t dstBase = (size_t)z * 2048 * 1024;
    int r0 = blockIdx.y * 32, c0 = blockIdx.x * 32;
    int tx = threadIdx.x, ty = threadIdx.y;   // 32 x 8
    #pragma unroll
    for (int i = 0; i < 32; i += 8)
        tile[ty+i][tx] = src[(size_t)(r0+ty+i)*srcLD + c0 + tx];
    __syncthreads();
    #pragma unroll
    for (int i = 0; i < 32; i += 8)
        dst[dstBase + (size_t)(c0+ty+i)*1024 + r0 + tx] = __float2bfloat16_rn(tile[tx][ty+i]);
}

// ---------------- Plain transpose fp32 -> bf16 (Wout) ----------------
__global__ void transpose_bf16(const float* __restrict__ src, __nv_bfloat16* __restrict__ dst,
                               int R, int C) {
    __shared__ float tile[32][33];
    int r0 = blockIdx.y * 32, c0 = blockIdx.x * 32;
    int tx = threadIdx.x, ty = threadIdx.y;   // 32 x 8
    #pragma unroll
    for (int i = 0; i < 32; i += 8)
        tile[ty+i][tx] = src[(size_t)(r0+ty+i)*C + c0 + tx];
    __syncthreads();
    #pragma unroll
    for (int i = 0; i < 32; i += 8)
        dst[(size_t)(c0+ty+i)*R + r0 + tx] = __float2bfloat16_rn(tile[tx][ty+i]);
}

// ---------------- Legacy-MMA bf16 GEMM: CTA 128x128, 4 warps of 64x64, 2 CTA/SM ----------------
// Same 3-stage double-sync pipeline as the measured-fast R3/R9 mainloop, but
// warp tile 64x64: 8 LDSM per 32 MMA (halves smem-read and address-ALU per FLOP).
#define BK 64
#define NST 3
#define AST (128*BK*2)         // 16384 bytes per A stage
#define BST (128*BK*2)         // 16384 bytes per B stage
#define GEMM_SMEM (NST*(AST+BST))   // 98304 = 96KB

__global__ void __launch_bounds__(128, 2)
gemm_bf16(const __nv_bfloat16* __restrict__ A, const __nv_bfloat16* __restrict__ B,
          float* __restrict__ C, int N, int K, int NIT,
          int mode, const float* __restrict__ resid) {
    extern __shared__ char smraw[];
    const uint32_t sbase = smem_u32(smraw);

    const int tid  = threadIdx.x;          // 0..127
    const int wid  = tid >> 5;             // 0..3
    const int lane = tid & 31;
    const int m0 = blockIdx.y * 128;
    const int n0 = blockIdx.x * 128;
    const int wm0 = (wid >> 1) * 64;       // warp row origin (0/64)
    const int wn0 = (wid & 1) * 64;        // warp col origin (0/64)
    const int blk = lane >> 3;             // 0..3
    const int lr8 = lane & 7;
    const int kb2 = (blk >> 1) * 16;       // +16B for k8..15 half

    // Hoisted fill addressing: 128 threads cover 16 rows/sweep, 8 sweeps per tile
    uint32_t sOff[8];
    uint32_t goA[8], goB[8];               // 32-bit element offsets from A / B
    {
        int r = tid >> 3, c = tid & 7;     // r 0..15, c 0..7
        #pragma unroll
        for (int i = 0; i < 8; i++) {
            int rr = r + i * 16;
            sOff[i] = (uint32_t)(rr * 128 + ((c ^ (rr & 7)) << 4));
            goA[i] = (uint32_t)((m0 + rr) * K + c * 8);
            goB[i] = (uint32_t)((n0 + rr) * K + c * 8);
        }
    }

    uint32_t offA[4], xrA[4], offB[4], xrB[4];
    #pragma unroll
    for (int mt = 0; mt < 4; mt++) {
        int r = wm0 + mt*16 + (blk & 1)*8 + lr8;
        offA[mt] = (uint32_t)r * 128u;
        xrA[mt]  = (uint32_t)(r & 7) << 4;
    }
    #pragma unroll
    for (int np = 0; np < 4; np++) {
        int r = wn0 + np*16 + (blk & 1)*8 + lr8;
        offB[np] = (uint32_t)r * 128u;
        xrB[np]  = (uint32_t)(r & 7) << 4;
    }

    float c[4][8][4];
    #pragma unroll
    for (int i = 0; i < 4; i++)
        #pragma unroll
        for (int j = 0; j < 8; j++)
            #pragma unroll
            for (int e = 0; e < 4; e++) c[i][j][e] = 0.0f;

    // Prologue: fill all 3 stages
    #pragma unroll
    for (int pf = 0; pf < NST; ++pf) {
        const uint32_t aS = sbase + pf*(AST+BST);
        const uint32_t bS = aS + AST;
        const uint32_t k0 = pf * BK;
        #pragma unroll
        for (int i = 0; i < 8; i++) cp16(aS + sOff[i], A + goA[i] + k0);
        #pragma unroll
        for (int i = 0; i < 8; i++) cp16(bS + sOff[i], B + goB[i] + k0);
        CP_COMMIT();
    }

    for (int it = 0; it < NIT; ++it) {
        const int s = it % NST;
        const uint32_t aS = sbase + s*(AST+BST);
        const uint32_t bS = aS + AST;

        int rem = NIT - 1 - it;
        if (rem >= 2)      asm volatile("cp.async.wait_group 2;" ::: "memory");
        else if (rem == 1) asm volatile("cp.async.wait_group 1;" ::: "memory");
        else               asm volatile("cp.async.wait_group 0;" ::: "memory");
        __syncthreads();

        #pragma unroll
        for (int kk = 0; kk < 4; ++kk) {
            uint32_t a[4][4], b[4][4];
            const uint32_t kbase = (uint32_t)(kk*32) + kb2;
            #pragma unroll
            for (int mt = 0; mt < 4; mt++)
                ldm_x4(a[mt], aS + offA[mt] + (kbase ^ xrA[mt]));
            #pragma unroll
            for (int np = 0; np < 4; np++)
                ldm_x4(b[np], bS + offB[np] + (kbase ^ xrB[np]));
            #pragma unroll
            for (int mt = 0; mt < 4; mt++)
                #pragma unroll
                for (int nt = 0; nt < 8; nt++) {
                    int np = nt >> 1, odd = nt & 1;
                    mma_bf16(c[mt][nt], a[mt], b[np][odd], b[np][2 + odd]);
                }
        }
        __syncthreads();   // everyone done reading stage s

        if (it + 3 < NIT) {
            const uint32_t k0 = (it + 3) * BK;
            #pragma unroll
            for (int i = 0; i < 8; i++) cp16(aS + sOff[i], A + goA[i] + k0);
            #pragma unroll
            for (int i = 0; i < 8; i++) cp16(bS + sOff[i], B + goB[i] + k0);
            CP_COMMIT();
        }
    }

    // Epilogue: direct float2 stores
    const int g = lane >> 2, tig = lane & 3;
    #pragma unroll
    for (int mt = 0; mt < 4; mt++) {
        int row = m0 + wm0 + mt*16 + g;
        #pragma unroll
        for (int nt = 0; nt < 8; nt++) {
            int col = n0 + wn0 + nt*8 + 2*tig;
            float v0 = c[mt][nt][0], v1 = c[mt][nt][1];
            float v2 = c[mt][nt][2], v3 = c[mt][nt][3];
            if (mode == 0) {
                bool sg = (col < 2048) || (col >= 4096);
                if (sg) { v0 = sigm(v0); v1 = sigm(v1); v2 = sigm(v2); v3 = sigm(v3); }
            } else {
                v0 += resid[(size_t)row * N + col];
                v1 += resid[(size_t)row * N + col + 1];
                v2 += resid[(size_t)(row+8) * N + col];
                v3 += resid[(size_t)(row+8) * N + col + 1];
            }
            *(float2*)(C + (size_t)row * N + col)     = make_float2(v0, v1);
            *(float2*)(C + (size_t)(row+8) * N + col) = make_float2(v2, v3);
        }
    }
}

// ---------------- Chunked linear-recurrence scan (R9 3-phase, measured-fast) ----------------
__global__ void scan_phase1(const float* __restrict__ C,
                            float* __restrict__ chA, float* __restrict__ chB) {
    int cidx  = blockIdx.x * blockDim.x + threadIdx.x;   // 0..2047
    int chunk = blockIdx.y;
    int b     = blockIdx.z;
    size_t base = (size_t)b * SEQ * NTOT;
    float Aacc = 1.0f, Bacc = 0.0f;
    int t0 = chunk * TCH;
    float kprev = (t0 == 0) ? 1.0f : C[base + (size_t)(t0-1) * NTOT + cidx];
    for (int tl = 0; tl < TCH; tl++) {
        int t = t0 + tl;
        size_t r = base + (size_t)t * NTOT;
        float Kc = C[r + cidx];
        float u  = C[r + 2048 + cidx];
        float gi = C[r + 4096 + cidx];
        float a  = (t == 0) ? 1.0f : kprev;
        kprev = Kc;
        float up = u * gi * (1.0f - Kc);
        Aacc = a * Aacc;
        Bacc = a * Bacc + up;
    }
    int idx = (b * NCH + chunk) * STATE + cidx;
    chA[idx] = Aacc;
    chB[idx] = Bacc;
}

__global__ void scan_phase2(const float* __restrict__ chA,
                            const float* __restrict__ chB,
                            float* __restrict__ hin) {
    int i = blockIdx.x * blockDim.x + threadIdx.x;   // b*2048+c
    int b = i >> 11, cidx = i & 2047;
    float h = 0.0f;
    for (int ch = 0; ch < NCH; ch++) {
        int idx = (b * NCH + ch) * STATE + cidx;
        hin[idx] = h;
        h = chA[idx] * h + chB[idx];
    }
}

__global__ void scan_phase3(const float* __restrict__ C,
                            const float* __restrict__ hin,
                            __nv_bfloat16* __restrict__ out1) {
    int cidx  = blockIdx.x * blockDim.x + threadIdx.x;
    int chunk = blockIdx.y;
    int b     = blockIdx.z;
    size_t base = (size_t)b * SEQ * NTOT;
    float h = hin[(b * NCH + chunk) * STATE + cidx];
    int t0 = chunk * TCH;
    float kprev = (t0 == 0) ? 1.0f : C[base + (size_t)(t0-1) * NTOT + cidx];
    for (int tl = 0; tl < TCH; tl++) {
        int t = t0 + tl;
        size_t r = base + (size_t)t * NTOT;
        float Kc = C[r + cidx];
        float u  = C[r + 2048 + cidx];
        float gi = C[r + 4096 + cidx];
        float go = C[r + 6144 + cidx];
        float a  = (t == 0) ? 1.0f : kprev;
        kprev = Kc;
        float up = u * gi * (1.0f - Kc);
        h = a * h + up;
        out1[((size_t)b * SEQ + t) * STATE + cidx] = __float2bfloat16_rn(h * go);
    }
}

// ---------------- Launch ----------------
extern "C" void kernel_launch(void* const* d_in, const int* in_sizes, int n_in,
                              void* d_out, int out_size) {
    const float* x    = (const float*)d_in[0];
    const float* ls   = (const float*)d_in[1];
    const float* rs   = (const float*)d_in[2];
    const float* ss   = (const float*)d_in[3];
    const float* Wk   = (const float*)d_in[4];
    const float* Wugg = (const float*)d_in[5];
    const float* Wout = (const float*)d_in[6];
    float* y = (float*)d_out;

    __nv_bfloat16 *p_xn, *p_WT, *p_WoutT, *p_out1;
    float *p_C, *p_chA, *p_chB, *p_hin;
    cudaGetSymbolAddress((void**)&p_xn,    g_xn);
    cudaGetSymbolAddress((void**)&p_WT,    g_WT);
    cudaGetSymbolAddress((void**)&p_WoutT, g_WoutT);
    cudaGetSymbolAddress((void**)&p_C,     g_C);
    cudaGetSymbolAddress((void**)&p_out1,  g_out1);
    cudaGetSymbolAddress((void**)&p_chA,   g_chA);
    cudaGetSymbolAddress((void**)&p_chB,   g_chB);
    cudaGetSymbolAddress((void**)&p_hin,   g_hin);

    cudaFuncSetAttribute(gemm_bf16, cudaFuncAttributeMaxDynamicSharedMemorySize, GEMM_SMEM);

    dim3 blk(32, 8);

    rmsnorm_kernel<<<ROWS, 256>>>(x, ls, rs, ss, p_xn);
    prep_WT<<<dim3(2048/32, 1024/32, 4), blk>>>(Wk, Wugg, p_WT);
    transpose_bf16<<<dim3(1024/32, 2048/32), blk>>>(Wout, p_WoutT, 2048, 1024);
    // global launch index 5 -> ncu profiles GEMM1
    gemm_bf16<<<dim3(NTOT/128, ROWS/128), 128, GEMM_SMEM>>>(p_xn, p_WT, p_C,
                                                            NTOT, DIMS, DIMS/BK, 0, nullptr);

    scan_phase1<<<dim3(STATE/256, NCH, BATCH), 256>>>(p_C, p_chA, p_chB);
    scan_phase2<<<(BATCH*STATE)/256, 256>>>(p_chA, p_chB, p_hin);
    scan_phase3<<<dim3(STATE/256, NCH, BATCH), 256>>>(p_C, p_hin, p_out1);

    gemm_bf16<<<dim3(DIMS/128, ROWS/128), 128, GEMM_SMEM>>>(p_out1, p_WoutT, y,
                                                            DIMS, STATE, STATE/BK, 1, x);
}

// round 12
// speedup vs baseline: 1.0995x; 1.0292x over previous
#include <cuda_runtime.h>
#include <cuda_bf16.h>
#include <math.h>
#include <stdint.h>

// ---------------- Problem constants ----------------
#define BATCH   4
#define SEQ     2048
#define ROWS    (BATCH*SEQ)      // 8192
#define DIMS    1024
#define STATE   2048             // 2*DIMS
#define NTOT    (4*STATE)        // 8192 logical GEMM1 columns [K|u|gin|gout]
#define TCH     128              // scan chunk length
#define NCH     (SEQ/TCH)        // 16 chunks

// ---------------- Scratch (device globals; no allocation allowed) ----------------
__device__ __nv_bfloat16 g_xn[(size_t)ROWS*DIMS];       // 16MB  normalized input (bf16)
__device__ __nv_bfloat16 g_WT[(size_t)NTOT*DIMS];       // 16MB  [Wk|Wugg]^T as [n,k] bf16
__device__ __nv_bfloat16 g_WoutT[(size_t)DIMS*STATE];   // 4MB   Wout^T as [n,k] bf16
__device__ float         g_CK [(size_t)ROWS*STATE];     // 64MB  sig(K)  fp32 (recurrence-critical)
__device__ __nv_bfloat16 g_CU [(size_t)ROWS*STATE];     // 32MB  u       bf16
__device__ __nv_bfloat16 g_CGI[(size_t)ROWS*STATE];     // 32MB  sig(gin)  bf16
__device__ __nv_bfloat16 g_CGO[(size_t)ROWS*STATE];     // 32MB  sig(gout) bf16
__device__ __nv_bfloat16 g_out1[(size_t)ROWS*STATE];    // 32MB  h*sig(gout) bf16
__device__ float g_chA[BATCH*NCH*STATE];
__device__ float g_chB[BATCH*NCH*STATE];
__device__ float g_hin[BATCH*NCH*STATE];

// ---------------- Helpers ----------------
__device__ __forceinline__ uint32_t smem_u32(const void* p) {
    uint32_t a;
    asm("{ .reg .u64 t; cvta.to.shared.u64 t, %1; cvt.u32.u64 %0, t; }" : "=r"(a) : "l"(p));
    return a;
}
__device__ __forceinline__ void cp16(uint32_t dst, const void* src) {
    asm volatile("cp.async.cg.shared.global [%0], [%1], 16;" :: "r"(dst), "l"(src) : "memory");
}
#define CP_COMMIT() asm volatile("cp.async.commit_group;" ::: "memory")

__device__ __forceinline__ void ldm_x4(uint32_t* r, uint32_t addr) {
    asm volatile("ldmatrix.sync.aligned.m8n8.x4.shared.b16 {%0,%1,%2,%3}, [%4];"
                 : "=r"(r[0]), "=r"(r[1]), "=r"(r[2]), "=r"(r[3]) : "r"(addr));
}
__device__ __forceinline__ void mma_bf16(float* c, const uint32_t* a,
                                         uint32_t b0, uint32_t b1) {
    asm volatile(
        "mma.sync.aligned.m16n8k16.row.col.f32.bf16.bf16.f32 "
        "{%0,%1,%2,%3},{%4,%5,%6,%7},{%8,%9},{%0,%1,%2,%3};"
        : "+f"(c[0]), "+f"(c[1]), "+f"(c[2]), "+f"(c[3])
        : "r"(a[0]), "r"(a[1]), "r"(a[2]), "r"(a[3]), "r"(b0), "r"(b1));
}
// Fast sigmoid: MUFU.EX2-based exp + MUFU.RCP division (~4 SASS ops).
__device__ __forceinline__ float sigm(float v) {
    return __fdividef(1.0f, 1.0f + __expf(-v));
}

// ---------------- RMS split norm -> bf16 ----------------
__global__ void rmsnorm_kernel(const float* __restrict__ x,
                               const float* __restrict__ ls,
                               const float* __restrict__ rs,
                               const float* __restrict__ ss,
                               __nv_bfloat16* __restrict__ xn) {
    __shared__ float wsum[8];
    int row = blockIdx.x;
    int tid = threadIdx.x;                 // 256 threads, 4 elems each
    const float* xr = x + (size_t)row * DIMS;
    float4 xv = ((const float4*)xr)[tid];
    float s = xv.x*xv.x + xv.y*xv.y + xv.z*xv.z + xv.w*xv.w;
    #pragma unroll
    for (int o = 16; o; o >>= 1) s += __shfl_xor_sync(0xffffffffu, s, o);
    if ((tid & 31) == 0) wsum[tid >> 5] = s;
    __syncthreads();
    int half = tid >> 7;
    float tot = wsum[half*4+0] + wsum[half*4+1] + wsum[half*4+2] + wsum[half*4+3];
    float n = sqrtf(tot) * 0.04419417382415922f + 1e-8f;   // 1/sqrt(512)
    float inv = 1.0f / n;
    const float* sc = half ? rs : ls;
    int jb = (tid*4) & 511;
    float4 scv = ((const float4*)sc)[jb >> 2];
    float4 ssv = ((const float4*)ss)[tid];
    __nv_bfloat162 p0 = __floats2bfloat162_rn(xv.x * scv.x * inv * ssv.x,
                                              xv.y * scv.y * inv * ssv.y);
    __nv_bfloat162 p1 = __floats2bfloat162_rn(xv.z * scv.z * inv * ssv.z,
                                              xv.w * scv.w * inv * ssv.w);
    __nv_bfloat162* dst = (__nv_bfloat162*)(xn + (size_t)row * DIMS);
    dst[tid*2]   = p0;
    dst[tid*2+1] = p1;
}

// ---------------- Fused weight-prep: transpose Wk + Wugg into g_WT (one launch) ----------------
__global__ void prep_WT(const float* __restrict__ Wk, const float* __restrict__ Wugg,
                        __nv_bfloat16* __restrict__ dst) {
    __shared__ float tile[32][33];
    int z = blockIdx.z;
    const float* src = (z == 0) ? Wk : (Wugg + (z - 1) * 2048);
    int srcLD = (z == 0) ? 2048 : 6144;
    size_t dstBase = (size_t)z * 2048 * 1024;
    int r0 = blockIdx.y * 32, c0 = blockIdx.x * 32;
    int tx = threadIdx.x, ty = threadIdx.y;   // 32 x 8
    #pragma unroll
    for (int i = 0; i < 32; i += 8)
        tile[ty+i][tx] = src[(size_t)(r0+ty+i)*srcLD + c0 + tx];
    __syncthreads();
    #pragma unroll
    for (int i = 0; i < 32; i += 8)
        dst[dstBase + (size_t)(c0+ty+i)*1024 + r0 + tx] = __float2bfloat16_rn(tile[tx][ty+i]);
}

// ---------------- Plain transpose fp32 -> bf16 (Wout) ----------------
__global__ void transpose_bf16(const float* __restrict__ src, __nv_bfloat16* __restrict__ dst,
                               int R, int C) {
    __shared__ float tile[32][33];
    int r0 = blockIdx.y * 32, c0 = blockIdx.x * 32;
    int tx = threadIdx.x, ty = threadIdx.y;   // 32 x 8
    #pragma unroll
    for (int i = 0; i < 32; i += 8)
        tile[ty+i][tx] = src[(size_t)(r0+ty+i)*C + c0 + tx];
    __syncthreads();
    #pragma unroll
    for (int i = 0; i < 32; i += 8)
        dst[(size_t)(c0+ty+i)*R + r0 + tx] = __float2bfloat16_rn(tile[tx][ty+i]);
}

// ---------------- Legacy-MMA bf16 GEMM: CTA 128x128, 4 warps of 64x64, 2 CTA/SM ----------------
// R11 mainloop (measured fast, frozen). mode 0: plane-split epilogue
// (CK fp32, CU/CGI/CGO bf16; plane uniform per CTA). mode 1: y = acc + resid.
#define BK 64
#define NST 3
#define AST (128*BK*2)         // 16384 bytes per A stage
#define BST (128*BK*2)         // 16384 bytes per B stage
#define GEMM_SMEM (NST*(AST+BST))   // 98304 = 96KB

__global__ void __launch_bounds__(128, 2)
gemm_bf16(const __nv_bfloat16* __restrict__ A, const __nv_bfloat16* __restrict__ B,
          int N, int K, int NIT, int mode,
          float* __restrict__ pK, __nv_bfloat16* __restrict__ pU,
          __nv_bfloat16* __restrict__ pGI, __nv_bfloat16* __restrict__ pGO,
          float* __restrict__ Cout, const float* __restrict__ resid) {
    extern __shared__ char smraw[];
    const uint32_t sbase = smem_u32(smraw);

    const int tid  = threadIdx.x;          // 0..127
    const int wid  = tid >> 5;             // 0..3
    const int lane = tid & 31;
    const int m0 = blockIdx.y * 128;
    const int n0 = blockIdx.x * 128;
    const int wm0 = (wid >> 1) * 64;       // warp row origin (0/64)
    const int wn0 = (wid & 1) * 64;        // warp col origin (0/64)
    const int blk = lane >> 3;             // 0..3
    const int lr8 = lane & 7;
    const int kb2 = (blk >> 1) * 16;       // +16B for k8..15 half

    // Hoisted fill addressing: 128 threads cover 16 rows/sweep, 8 sweeps per tile
    uint32_t sOff[8];
    uint32_t goA[8], goB[8];               // 32-bit element offsets from A / B
    {
        int r = tid >> 3, c = tid & 7;     // r 0..15, c 0..7
        #pragma unroll
        for (int i = 0; i < 8; i++) {
            int rr = r + i * 16;
            sOff[i] = (uint32_t)(rr * 128 + ((c ^ (rr & 7)) << 4));
            goA[i] = (uint32_t)((m0 + rr) * K + c * 8);
            goB[i] = (uint32_t)((n0 + rr) * K + c * 8);
        }
    }

    uint32_t offA[4], xrA[4], offB[4], xrB[4];
    #pragma unroll
    for (int mt = 0; mt < 4; mt++) {
        int r = wm0 + mt*16 + (blk & 1)*8 + lr8;
        offA[mt] = (uint32_t)r * 128u;
        xrA[mt]  = (uint32_t)(r & 7) << 4;
    }
    #pragma unroll
    for (int np = 0; np < 4; np++) {
        int r = wn0 + np*16 + (blk & 1)*8 + lr8;
        offB[np] = (uint32_t)r * 128u;
        xrB[np]  = (uint32_t)(r & 7) << 4;
    }

    float c[4][8][4];
    #pragma unroll
    for (int i = 0; i < 4; i++)
        #pragma unroll
        for (int j = 0; j < 8; j++)
            #pragma unroll
            for (int e = 0; e < 4; e++) c[i][j][e] = 0.0f;

    // Prologue: fill all 3 stages
    #pragma unroll
    for (int pf = 0; pf < NST; ++pf) {
        const uint32_t aS = sbase + pf*(AST+BST);
        const uint32_t bS = aS + AST;
        const uint32_t k0 = pf * BK;
        #pragma unroll
        for (int i = 0; i < 8; i++) cp16(aS + sOff[i], A + goA[i] + k0);
        #pragma unroll
        for (int i = 0; i < 8; i++) cp16(bS + sOff[i], B + goB[i] + k0);
        CP_COMMIT();
    }

    for (int it = 0; it < NIT; ++it) {
        const int s = it % NST;
        const uint32_t aS = sbase + s*(AST+BST);
        const uint32_t bS = aS + AST;

        int rem = NIT - 1 - it;
        if (rem >= 2)      asm volatile("cp.async.wait_group 2;" ::: "memory");
        else if (rem == 1) asm volatile("cp.async.wait_group 1;" ::: "memory");
        else               asm volatile("cp.async.wait_group 0;" ::: "memory");
        __syncthreads();

        #pragma unroll
        for (int kk = 0; kk < 4; ++kk) {
            uint32_t a[4][4], b[4][4];
            const uint32_t kbase = (uint32_t)(kk*32) + kb2;
            #pragma unroll
            for (int mt = 0; mt < 4; mt++)
                ldm_x4(a[mt], aS + offA[mt] + (kbase ^ xrA[mt]));
            #pragma unroll
            for (int np = 0; np < 4; np++)
                ldm_x4(b[np], bS + offB[np] + (kbase ^ xrB[np]));
            #pragma unroll
            for (int mt = 0; mt < 4; mt++)
                #pragma unroll
                for (int nt = 0; nt < 8; nt++) {
                    int np = nt >> 1, odd = nt & 1;
                    mma_bf16(c[mt][nt], a[mt], b[np][odd], b[np][2 + odd]);
                }
        }
        __syncthreads();   // everyone done reading stage s

        if (it + 3 < NIT) {
            const uint32_t k0 = (it + 3) * BK;
            #pragma unroll
            for (int i = 0; i < 8; i++) cp16(aS + sOff[i], A + goA[i] + k0);
            #pragma unroll
            for (int i = 0; i < 8; i++) cp16(bS + sOff[i], B + goB[i] + k0);
            CP_COMMIT();
        }
    }

    // Epilogue
    const int g = lane >> 2, tig = lane & 3;
    if (mode == 0) {
        // CTA's 128-col tile lies in exactly one 2048-wide plane
        const int plane = n0 >> 11;          // 0:K 1:u 2:gin 3:gout
        const int p0 = n0 & 2047;
        if (plane == 0) {
            #pragma unroll
            for (int mt = 0; mt < 4; mt++) {
                int row = m0 + wm0 + mt*16 + g;
                #pragma unroll
                for (int nt = 0; nt < 8; nt++) {
                    int pcol = p0 + wn0 + nt*8 + 2*tig;
                    float v0 = sigm(c[mt][nt][0]), v1 = sigm(c[mt][nt][1]);
                    float v2 = sigm(c[mt][nt][2]), v3 = sigm(c[mt][nt][3]);
                    *(float2*)(pK + (size_t)row * STATE + pcol)     = make_float2(v0, v1);
                    *(float2*)(pK + (size_t)(row+8) * STATE + pcol) = make_float2(v2, v3);
                }
            }
        } else {
            __nv_bfloat16* dst = (plane == 1) ? pU : ((plane == 2) ? pGI : pGO);
            const bool sg = (plane >= 2);
            #pragma unroll
            for (int mt = 0; mt < 4; mt++) {
                int row = m0 + wm0 + mt*16 + g;
                #pragma unroll
                for (int nt = 0; nt < 8; nt++) {
                    int pcol = p0 + wn0 + nt*8 + 2*tig;
                    float v0 = c[mt][nt][0], v1 = c[mt][nt][1];
                    float v2 = c[mt][nt][2], v3 = c[mt][nt][3];
                    if (sg) { v0 = sigm(v0); v1 = sigm(v1); v2 = sigm(v2); v3 = sigm(v3); }
                    *(__nv_bfloat162*)(dst + (size_t)row * STATE + pcol)
                        = __floats2bfloat162_rn(v0, v1);
                    *(__nv_bfloat162*)(dst + (size_t)(row+8) * STATE + pcol)
                        = __floats2bfloat162_rn(v2, v3);
                }
            }
        }
    } else {
        #pragma unroll
        for (int mt = 0; mt < 4; mt++) {
            int row = m0 + wm0 + mt*16 + g;
            #pragma unroll
            for (int nt = 0; nt < 8; nt++) {
                int col = n0 + wn0 + nt*8 + 2*tig;
                float v0 = c[mt][nt][0] + resid[(size_t)row * N + col];
                float v1 = c[mt][nt][1] + resid[(size_t)row * N + col + 1];
                float v2 = c[mt][nt][2] + resid[(size_t)(row+8) * N + col];
                float v3 = c[mt][nt][3] + resid[(size_t)(row+8) * N + col + 1];
                *(float2*)(Cout + (size_t)row * N + col)     = make_float2(v0, v1);
                *(float2*)(Cout + (size_t)(row+8) * N + col) = make_float2(v2, v3);
            }
        }
    }
}

// ---------------- Chunked linear-recurrence scan (CK fp32, CU/CGI/CGO bf16) ----------------
__global__ void scan_phase1(const float* __restrict__ CK,
                            const __nv_bfloat16* __restrict__ CU,
                            const __nv_bfloat16* __restrict__ CGI,
                            float* __restrict__ chA, float* __restrict__ chB) {
    int cidx  = blockIdx.x * blockDim.x + threadIdx.x;   // 0..2047
    int chunk = blockIdx.y;
    int b     = blockIdx.z;
    float Aacc = 1.0f, Bacc = 0.0f;
    int t0 = chunk * TCH;
    size_t row0 = (size_t)b * SEQ + t0;
    float kprev = (t0 == 0) ? 1.0f : CK[(row0 - 1) * STATE + cidx];
    for (int tl = 0; tl < TCH; tl++) {
        size_t r = (row0 + tl) * STATE + cidx;
        float Kc = CK[r];
        float u  = __bfloat162float(CU[r]);
        float gi = __bfloat162float(CGI[r]);
        float a  = (t0 + tl == 0) ? 1.0f : kprev;
        kprev = Kc;
        float up = u * gi * (1.0f - Kc);
        Aacc = a * Aacc;
        Bacc = a * Bacc + up;
    }
    int idx = (b * NCH + chunk) * STATE + cidx;
    chA[idx] = Aacc;
    chB[idx] = Bacc;
}

__global__ void scan_phase2(const float* __restrict__ chA,
                            const float* __restrict__ chB,
                            float* __restrict__ hin) {
    int i = blockIdx.x * blockDim.x + threadIdx.x;   // b*2048+c
    int b = i >> 11, cidx = i & 2047;
    float h = 0.0f;
    for (int ch = 0; ch < NCH; ch++) {
        int idx = (b * NCH + ch) * STATE + cidx;
        hin[idx] = h;
        h = chA[idx] * h + chB[idx];
    }
}

__global__ void scan_phase3(const float* __restrict__ CK,
                            const __nv_bfloat16* __restrict__ CU,
                            const __nv_bfloat16* __restrict__ CGI,
                            const __nv_bfloat16* __restrict__ CGO,
                            const float* __restrict__ hin,
                            __nv_bfloat16* __restrict__ out1) {
    int cidx  = blockIdx.x * blockDim.x + threadIdx.x;
    int chunk = blockIdx.y;
    int b     = blockIdx.z;
    float h = hin[(b * NCH + chunk) * STATE + cidx];
    int t0 = chunk * TCH;
    size_t row0 = (size_t)b * SEQ + t0;
    float kprev = (t0 == 0) ? 1.0f : CK[(row0 - 1) * STATE + cidx];
    for (int tl = 0; tl < TCH; tl++) {
        size_t r = (row0 + tl) * STATE + cidx;
        float Kc = CK[r];
        float u  = __bfloat162float(CU[r]);
        float gi = __bfloat162float(CGI[r]);
        float go = __bfloat162float(CGO[r]);
        float a  = (t0 + tl == 0) ? 1.0f : kprev;
        kprev = Kc;
        float up = u * gi * (1.0f - Kc);
        h = a * h + up;
        out1[r] = __float2bfloat16_rn(h * go);
    }
}

// ---------------- Launch ----------------
extern "C" void kernel_launch(void* const* d_in, const int* in_sizes, int n_in,
                              void* d_out, int out_size) {
    const float* x    = (const float*)d_in[0];
    const float* ls   = (const float*)d_in[1];
    const float* rs   = (const float*)d_in[2];
    const float* ss   = (const float*)d_in[3];
    const float* Wk   = (const float*)d_in[4];
    const float* Wugg = (const float*)d_in[5];
    const float* Wout = (const float*)d_in[6];
    float* y = (float*)d_out;

    __nv_bfloat16 *p_xn, *p_WT, *p_WoutT, *p_out1, *p_CU, *p_CGI, *p_CGO;
    float *p_CK, *p_chA, *p_chB, *p_hin;
    cudaGetSymbolAddress((void**)&p_xn,    g_xn);
    cudaGetSymbolAddress((void**)&p_WT,    g_WT);
    cudaGetSymbolAddress((void**)&p_WoutT, g_WoutT);
    cudaGetSymbolAddress((void**)&p_CK,    g_CK);
    cudaGetSymbolAddress((void**)&p_CU,    g_CU);
    cudaGetSymbolAddress((void**)&p_CGI,   g_CGI);
    cudaGetSymbolAddress((void**)&p_CGO,   g_CGO);
    cudaGetSymbolAddress((void**)&p_out1,  g_out1);
    cudaGetSymbolAddress((void**)&p_chA,   g_chA);
    cudaGetSymbolAddress((void**)&p_chB,   g_chB);
    cudaGetSymbolAddress((void**)&p_hin,   g_hin);

    cudaFuncSetAttribute(gemm_bf16, cudaFuncAttributeMaxDynamicSharedMemorySize, GEMM_SMEM);

    dim3 blk(32, 8);

    rmsnorm_kernel<<<ROWS, 256>>>(x, ls, rs, ss, p_xn);
    prep_WT<<<dim3(2048/32, 1024/32, 4), blk>>>(Wk, Wugg, p_WT);
    transpose_bf16<<<dim3(1024/32, 2048/32), blk>>>(Wout, p_WoutT, 2048, 1024);
    // global launch index 5 -> ncu profiles GEMM1
    gemm_bf16<<<dim3(NTOT/128, ROWS/128), 128, GEMM_SMEM>>>(
        p_xn, p_WT, NTOT, DIMS, DIMS/BK, 0,
        p_CK, p_CU, p_CGI, p_CGO, nullptr, nullptr);

    scan_phase1<<<dim3(STATE/256, NCH, BATCH), 256>>>(p_CK, p_CU, p_CGI, p_chA, p_chB);
    scan_phase2<<<(BATCH*STATE)/256, 256>>>(p_chA, p_chB, p_hin);
    scan_phase3<<<dim3(STATE/256, NCH, BATCH), 256>>>(p_CK, p_CU, p_CGI, p_CGO, p_hin, p_out1);

    gemm_bf16<<<dim3(DIMS/128, ROWS/128), 128, GEMM_SMEM>>>(
        p_out1, p_WoutT, DIMS, STATE, STATE/BK, 1,
        nullptr, nullptr, nullptr, nullptr, y, x);
}

// round 13
// speedup vs baseline: 1.1204x; 1.0189x over previous
#include <cuda_runtime.h>
#include <cuda_bf16.h>
#include <math.h>
#include <stdint.h>

// ---------------- Problem constants ----------------
#define BATCH   4
#define SEQ     2048
#define ROWS    (BATCH*SEQ)      // 8192
#define DIMS    1024
#define STATE   2048             // 2*DIMS
#define NTOT    (4*STATE)        // 8192 logical GEMM1 columns [K | u,gin interleaved | gout]
#define TCH     128              // scan chunk length
#define NCH     (SEQ/TCH)        // 16 chunks

// ---------------- Scratch (device globals; no allocation allowed) ----------------
__device__ __nv_bfloat16 g_xn[(size_t)ROWS*DIMS];       // 16MB  normalized input (bf16)
__device__ __nv_bfloat16 g_WT[(size_t)NTOT*DIMS];       // 16MB  packed weights^T bf16
__device__ __nv_bfloat16 g_WoutT[(size_t)DIMS*STATE];   // 4MB   Wout^T as [n,k] bf16
__device__ __nv_bfloat16 g_CD [(size_t)ROWS*STATE];     // 32MB  d = 1-sig(K) bf16 (rel-in-d precise)
__device__ __nv_bfloat16 g_CU2[(size_t)ROWS*STATE];     // 32MB  u2 = u*sig(gin) bf16
__device__ __nv_bfloat16 g_CGO[(size_t)ROWS*STATE];     // 32MB  sig(gout) bf16
__device__ __nv_bfloat16 g_out1[(size_t)ROWS*STATE];    // 32MB  h*sig(gout) bf16
__device__ float g_chA[BATCH*NCH*STATE];
__device__ float g_chB[BATCH*NCH*STATE];
__device__ float g_hin[BATCH*NCH*STATE];

// ---------------- Helpers ----------------
__device__ __forceinline__ uint32_t smem_u32(const void* p) {
    uint32_t a;
    asm("{ .reg .u64 t; cvta.to.shared.u64 t, %1; cvt.u32.u64 %0, t; }" : "=r"(a) : "l"(p));
    return a;
}
__device__ __forceinline__ void cp16(uint32_t dst, const void* src) {
    asm volatile("cp.async.cg.shared.global [%0], [%1], 16;" :: "r"(dst), "l"(src) : "memory");
}
#define CP_COMMIT() asm volatile("cp.async.commit_group;" ::: "memory")

__device__ __forceinline__ void ldm_x4(uint32_t* r, uint32_t addr) {
    asm volatile("ldmatrix.sync.aligned.m8n8.x4.shared.b16 {%0,%1,%2,%3}, [%4];"
                 : "=r"(r[0]), "=r"(r[1]), "=r"(r[2]), "=r"(r[3]) : "r"(addr));
}
__device__ __forceinline__ void mma_bf16(float* c, const uint32_t* a,
                                         uint32_t b0, uint32_t b1) {
    asm volatile(
        "mma.sync.aligned.m16n8k16.row.col.f32.bf16.bf16.f32 "
        "{%0,%1,%2,%3},{%4,%5,%6,%7},{%8,%9},{%0,%1,%2,%3};"
        : "+f"(c[0]), "+f"(c[1]), "+f"(c[2]), "+f"(c[3])
        : "r"(a[0]), "r"(a[1]), "r"(a[2]), "r"(a[3]), "r"(b0), "r"(b1));
}
// Fast sigmoid: MUFU.EX2-based exp + MUFU.RCP division (~4 SASS ops).
__device__ __forceinline__ float sigm(float v) {
    return __fdividef(1.0f, 1.0f + __expf(-v));
}

// ---------------- RMS split norm -> bf16 ----------------
__global__ void rmsnorm_kernel(const float* __restrict__ x,
                               const float* __restrict__ ls,
                               const float* __restrict__ rs,
                               const float* __restrict__ ss,
                               __nv_bfloat16* __restrict__ xn) {
    __shared__ float wsum[8];
    int row = blockIdx.x;
    int tid = threadIdx.x;                 // 256 threads, 4 elems each
    const float* xr = x + (size_t)row * DIMS;
    float4 xv = ((const float4*)xr)[tid];
    float s = xv.x*xv.x + xv.y*xv.y + xv.z*xv.z + xv.w*xv.w;
    #pragma unroll
    for (int o = 16; o; o >>= 1) s += __shfl_xor_sync(0xffffffffu, s, o);
    if ((tid & 31) == 0) wsum[tid >> 5] = s;
    __syncthreads();
    int half = tid >> 7;
    float tot = wsum[half*4+0] + wsum[half*4+1] + wsum[half*4+2] + wsum[half*4+3];
    float n = sqrtf(tot) * 0.04419417382415922f + 1e-8f;   // 1/sqrt(512)
    float inv = 1.0f / n;
    const float* sc = half ? rs : ls;
    int jb = (tid*4) & 511;
    float4 scv = ((const float4*)sc)[jb >> 2];
    float4 ssv = ((const float4*)ss)[tid];
    __nv_bfloat162 p0 = __floats2bfloat162_rn(xv.x * scv.x * inv * ssv.x,
                                              xv.y * scv.y * inv * ssv.y);
    __nv_bfloat162 p1 = __floats2bfloat162_rn(xv.z * scv.z * inv * ssv.z,
                                              xv.w * scv.w * inv * ssv.w);
    __nv_bfloat162* dst = (__nv_bfloat162*)(xn + (size_t)row * DIMS);
    dst[tid*2]   = p0;
    dst[tid*2+1] = p1;
}

// ---------------- Weight prep with u/gin interleave ----------------
// z=0: Wk col c           -> WT row c                 (d-plane logits)
// z=1: Wugg col c         -> WT row 2048 + 2c         (u)
// z=2: Wugg col 2048+c    -> WT row 2048 + 2c + 1     (gin)
// z=3: Wugg col 4096+c    -> WT row 6144 + c          (gout)
__global__ void prep_WT(const float* __restrict__ Wk, const float* __restrict__ Wugg,
                        __nv_bfloat16* __restrict__ dst) {
    __shared__ float tile[32][33];
    int z = blockIdx.z;
    const float* src = (z == 0) ? Wk : (Wugg + (z - 1) * 2048);
    int srcLD = (z == 0) ? 2048 : 6144;
    int r0 = blockIdx.y * 32, c0 = blockIdx.x * 32;
    int tx = threadIdx.x, ty = threadIdx.y;   // 32 x 8
    #pragma unroll
    for (int i = 0; i < 32; i += 8)
        tile[ty+i][tx] = src[(size_t)(r0+ty+i)*srcLD + c0 + tx];
    __syncthreads();
    #pragma unroll
    for (int i = 0; i < 32; i += 8) {
        int c = c0 + ty + i;
        int dstRow;
        if      (z == 0) dstRow = c;
        else if (z == 1) dstRow = 2048 + 2*c;
        else if (z == 2) dstRow = 2048 + 2*c + 1;
        else             dstRow = 6144 + c;
        dst[(size_t)dstRow*1024 + r0 + tx] = __float2bfloat16_rn(tile[tx][ty+i]);
    }
}

// ---------------- Plain transpose fp32 -> bf16 (Wout) ----------------
__global__ void transpose_bf16(const float* __restrict__ src, __nv_bfloat16* __restrict__ dst,
                               int R, int C) {
    __shared__ float tile[32][33];
    int r0 = blockIdx.y * 32, c0 = blockIdx.x * 32;
    int tx = threadIdx.x, ty = threadIdx.y;   // 32 x 8
    #pragma unroll
    for (int i = 0; i < 32; i += 8)
        tile[ty+i][tx] = src[(size_t)(r0+ty+i)*C + c0 + tx];
    __syncthreads();
    #pragma unroll
    for (int i = 0; i < 32; i += 8)
        dst[(size_t)(c0+ty+i)*R + r0 + tx] = __float2bfloat16_rn(tile[tx][ty+i]);
}

// ---------------- Legacy-MMA bf16 GEMM: CTA 128x128, 4 warps of 64x64, 2 CTA/SM ----------------
// R11/R12 mainloop (measured fast, frozen).
// mode 0: plane epilogue -> CD bf16 (d=sig(-K)), CU2 bf16 (u*sig(gin)), CGO bf16 (sig(gout))
// mode 1: y = acc + resid (fp32)
#define BK 64
#define NST 3
#define AST (128*BK*2)         // 16384 bytes per A stage
#define BST (128*BK*2)         // 16384 bytes per B stage
#define GEMM_SMEM (NST*(AST+BST))   // 98304 = 96KB

__global__ void __launch_bounds__(128, 2)
gemm_bf16(const __nv_bfloat16* __restrict__ A, const __nv_bfloat16* __restrict__ B,
          int N, int K, int NIT, int mode,
          __nv_bfloat16* __restrict__ pD, __nv_bfloat16* __restrict__ pU2,
          __nv_bfloat16* __restrict__ pGO,
          float* __restrict__ Cout, const float* __restrict__ resid) {
    extern __shared__ char smraw[];
    const uint32_t sbase = smem_u32(smraw);

    const int tid  = threadIdx.x;          // 0..127
    const int wid  = tid >> 5;             // 0..3
    const int lane = tid & 31;
    const int m0 = blockIdx.y * 128;
    const int n0 = blockIdx.x * 128;
    const int wm0 = (wid >> 1) * 64;       // warp row origin (0/64)
    const int wn0 = (wid & 1) * 64;        // warp col origin (0/64)
    const int blk = lane >> 3;             // 0..3
    const int lr8 = lane & 7;
    const int kb2 = (blk >> 1) * 16;       // +16B for k8..15 half

    // Hoisted fill addressing: 128 threads cover 16 rows/sweep, 8 sweeps per tile
    uint32_t sOff[8];
    uint32_t goA[8], goB[8];
    {
        int r = tid >> 3, c = tid & 7;
        #pragma unroll
        for (int i = 0; i < 8; i++) {
            int rr = r + i * 16;
            sOff[i] = (uint32_t)(rr * 128 + ((c ^ (rr & 7)) << 4));
            goA[i] = (uint32_t)((m0 + rr) * K + c * 8);
            goB[i] = (uint32_t)((n0 + rr) * K + c * 8);
        }
    }

    uint32_t offA[4], xrA[4], offB[4], xrB[4];
    #pragma unroll
    for (int mt = 0; mt < 4; mt++) {
        int r = wm0 + mt*16 + (blk & 1)*8 + lr8;
        offA[mt] = (uint32_t)r * 128u;
        xrA[mt]  = (uint32_t)(r & 7) << 4;
    }
    #pragma unroll
    for (int np = 0; np < 4; np++) {
        int r = wn0 + np*16 + (blk & 1)*8 + lr8;
        offB[np] = (uint32_t)r * 128u;
        xrB[np]  = (uint32_t)(r & 7) << 4;
    }

    float c[4][8][4];
    #pragma unroll
    for (int i = 0; i < 4; i++)
        #pragma unroll
        for (int j = 0; j < 8; j++)
            #pragma unroll
            for (int e = 0; e < 4; e++) c[i][j][e] = 0.0f;

    // Prologue: fill all 3 stages
    #pragma unroll
    for (int pf = 0; pf < NST; ++pf) {
        const uint32_t aS = sbase + pf*(AST+BST);
        const uint32_t bS = aS + AST;
        const uint32_t k0 = pf * BK;
        #pragma unroll
        for (int i = 0; i < 8; i++) cp16(aS + sOff[i], A + goA[i] + k0);
        #pragma unroll
        for (int i = 0; i < 8; i++) cp16(bS + sOff[i], B + goB[i] + k0);
        CP_COMMIT();
    }

    for (int it = 0; it < NIT; ++it) {
        const int s = it % NST;
        const uint32_t aS = sbase + s*(AST+BST);
        const uint32_t bS = aS + AST;

        int rem = NIT - 1 - it;
        if (rem >= 2)      asm volatile("cp.async.wait_group 2;" ::: "memory");
        else if (rem == 1) asm volatile("cp.async.wait_group 1;" ::: "memory");
        else               asm volatile("cp.async.wait_group 0;" ::: "memory");
        __syncthreads();

        #pragma unroll
        for (int kk = 0; kk < 4; ++kk) {
            uint32_t a[4][4], b[4][4];
            const uint32_t kbase = (uint32_t)(kk*32) + kb2;
            #pragma unroll
            for (int mt = 0; mt < 4; mt++)
                ldm_x4(a[mt], aS + offA[mt] + (kbase ^ xrA[mt]));
            #pragma unroll
            for (int np = 0; np < 4; np++)
                ldm_x4(b[np], bS + offB[np] + (kbase ^ xrB[np]));
            #pragma unroll
            for (int mt = 0; mt < 4; mt++)
                #pragma unroll
                for (int nt = 0; nt < 8; nt++) {
                    int np = nt >> 1, odd = nt & 1;
                    mma_bf16(c[mt][nt], a[mt], b[np][odd], b[np][2 + odd]);
                }
        }
        __syncthreads();   // everyone done reading stage s

        if (it + 3 < NIT) {
            const uint32_t k0 = (it + 3) * BK;
            #pragma unroll
            for (int i = 0; i < 8; i++) cp16(aS + sOff[i], A + goA[i] + k0);
            #pragma unroll
            for (int i = 0; i < 8; i++) cp16(bS + sOff[i], B + goB[i] + k0);
            CP_COMMIT();
        }
    }

    // Epilogue
    const int g = lane >> 2, tig = lane & 3;
    if (mode == 0) {
        // Column layout: [0,2048) K-logits -> d ; [2048,6144) interleaved (u,gin) -> u2 ;
        // [6144,8192) gout -> sig. A 128-wide CTA tile never straddles planes.
        if (n0 < 2048) {
            #pragma unroll
            for (int mt = 0; mt < 4; mt++) {
                int row = m0 + wm0 + mt*16 + g;
                #pragma unroll
                for (int nt = 0; nt < 8; nt++) {
                    int st = n0 + wn0 + nt*8 + 2*tig;
                    // d = 1 - sig(v) = sig(-v): full relative precision near a->1
                    float d0 = sigm(-c[mt][nt][0]), d1 = sigm(-c[mt][nt][1]);
                    float d2 = sigm(-c[mt][nt][2]), d3 = sigm(-c[mt][nt][3]);
                    *(__nv_bfloat162*)(pD + (size_t)row * STATE + st)
                        = __floats2bfloat162_rn(d0, d1);
                    *(__nv_bfloat162*)(pD + (size_t)(row+8) * STATE + st)
                        = __floats2bfloat162_rn(d2, d3);
                }
            }
        } else if (n0 < 6144) {
            #pragma unroll
            for (int mt = 0; mt < 4; mt++) {
                int row = m0 + wm0 + mt*16 + g;
                #pragma unroll
                for (int nt = 0; nt < 8; nt++) {
                    int col = n0 + wn0 + nt*8 + 2*tig;    // even: u at col, gin at col+1
                    int st = (col - 2048) >> 1;
                    float u20 = c[mt][nt][0] * sigm(c[mt][nt][1]);
                    float u21 = c[mt][nt][2] * sigm(c[mt][nt][3]);
                    pU2[(size_t)row * STATE + st]     = __float2bfloat16_rn(u20);
                    pU2[(size_t)(row+8) * STATE + st] = __float2bfloat16_rn(u21);
                }
            }
        } else {
            #pragma unroll
            for (int mt = 0; mt < 4; mt++) {
                int row = m0 + wm0 + mt*16 + g;
                #pragma unroll
                for (int nt = 0; nt < 8; nt++) {
                    int st = (n0 - 6144) + wn0 + nt*8 + 2*tig;
                    float v0 = sigm(c[mt][nt][0]), v1 = sigm(c[mt][nt][1]);
                    float v2 = sigm(c[mt][nt][2]), v3 = sigm(c[mt][nt][3]);
                    *(__nv_bfloat162*)(pGO + (size_t)row * STATE + st)
                        = __floats2bfloat162_rn(v0, v1);
                    *(__nv_bfloat162*)(pGO + (size_t)(row+8) * STATE + st)
                        = __floats2bfloat162_rn(v2, v3);
                }
            }
        }
    } else {
        #pragma unroll
        for (int mt = 0; mt < 4; mt++) {
            int row = m0 + wm0 + mt*16 + g;
            #pragma unroll
            for (int nt = 0; nt < 8; nt++) {
                int col = n0 + wn0 + nt*8 + 2*tig;
                float v0 = c[mt][nt][0] + resid[(size_t)row * N + col];
                float v1 = c[mt][nt][1] + resid[(size_t)row * N + col + 1];
                float v2 = c[mt][nt][2] + resid[(size_t)(row+8) * N + col];
                float v3 = c[mt][nt][3] + resid[(size_t)(row+8) * N + col + 1];
                *(float2*)(Cout + (size_t)row * N + col)     = make_float2(v0, v1);
                *(float2*)(Cout + (size_t)(row+8) * N + col) = make_float2(v2, v3);
            }
        }
    }
}

// ---------------- Chunked linear-recurrence scan (d, u2, gout all bf16) ----------------
// a_t = 1 - d_{t-1}; u'_t = u2_t * d_t; h_t = a_t h_{t-1} + u'_t
__global__ void scan_phase1(const __nv_bfloat16* __restrict__ CD,
                            const __nv_bfloat16* __restrict__ CU2,
                            float* __restrict__ chA, float* __restrict__ chB) {
    int cidx  = blockIdx.x * blockDim.x + threadIdx.x;   // 0..2047
    int chunk = blockIdx.y;
    int b     = blockIdx.z;
    float Aacc = 1.0f, Bacc = 0.0f;
    int t0 = chunk * TCH;
    size_t row0 = (size_t)b * SEQ + t0;
    float dprev = (t0 == 0) ? 0.0f : __bfloat162float(CD[(row0 - 1) * STATE + cidx]);
    for (int tl = 0; tl < TCH; tl++) {
        size_t r = (row0 + tl) * STATE + cidx;
        float d  = __bfloat162float(CD[r]);
        float u2 = __bfloat162float(CU2[r]);
        float a  = 1.0f - dprev;
        dprev = d;
        float up = u2 * d;
        Aacc = a * Aacc;
        Bacc = a * Bacc + up;
    }
    int idx = (b * NCH + chunk) * STATE + cidx;
    chA[idx] = Aacc;
    chB[idx] = Bacc;
}

__global__ void scan_phase2(const float* __restrict__ chA,
                            const float* __restrict__ chB,
                            float* __restrict__ hin) {
    int i = blockIdx.x * blockDim.x + threadIdx.x;   // b*2048+c
    int b = i >> 11, cidx = i & 2047;
    float h = 0.0f;
    for (int ch = 0; ch < NCH; ch++) {
        int idx = (b * NCH + ch) * STATE + cidx;
        hin[idx] = h;
        h = chA[idx] * h + chB[idx];
    }
}

__global__ void scan_phase3(const __nv_bfloat16* __restrict__ CD,
                            const __nv_bfloat16* __restrict__ CU2,
                            const __nv_bfloat16* __restrict__ CGO,
                            const float* __restrict__ hin,
                            __nv_bfloat16* __restrict__ out1) {
    int cidx  = blockIdx.x * blockDim.x + threadIdx.x;
    int chunk = blockIdx.y;
    int b     = blockIdx.z;
    float h = hin[(b * NCH + chunk) * STATE + cidx];
    int t0 = chunk * TCH;
    size_t row0 = (size_t)b * SEQ + t0;
    float dprev = (t0 == 0) ? 0.0f : __bfloat162float(CD[(row0 - 1) * STATE + cidx]);
    for (int tl = 0; tl < TCH; tl++) {
        size_t r = (row0 + tl) * STATE + cidx;
        float d  = __bfloat162float(CD[r]);
        float u2 = __bfloat162float(CU2[r]);
        float go = __bfloat162float(CGO[r]);
        float a  = 1.0f - dprev;
        dprev = d;
        h = a * h + u2 * d;
        out1[r] = __float2bfloat16_rn(h * go);
    }
}

// ---------------- Launch ----------------
extern "C" void kernel_launch(void* const* d_in, const int* in_sizes, int n_in,
                              void* d_out, int out_size) {
    const float* x    = (const float*)d_in[0];
    const float* ls   = (const float*)d_in[1];
    const float* rs   = (const float*)d_in[2];
    const float* ss   = (const float*)d_in[3];
    const float* Wk   = (const float*)d_in[4];
    const float* Wugg = (const float*)d_in[5];
    const float* Wout = (const float*)d_in[6];
    float* y = (float*)d_out;

    __nv_bfloat16 *p_xn, *p_WT, *p_WoutT, *p_out1, *p_CD, *p_CU2, *p_CGO;
    float *p_chA, *p_chB, *p_hin;
    cudaGetSymbolAddress((void**)&p_xn,    g_xn);
    cudaGetSymbolAddress((void**)&p_WT,    g_WT);
    cudaGetSymbolAddress((void**)&p_WoutT, g_WoutT);
    cudaGetSymbolAddress((void**)&p_CD,    g_CD);
    cudaGetSymbolAddress((void**)&p_CU2,   g_CU2);
    cudaGetSymbolAddress((void**)&p_CGO,   g_CGO);
    cudaGetSymbolAddress((void**)&p_out1,  g_out1);
    cudaGetSymbolAddress((void**)&p_chA,   g_chA);
    cudaGetSymbolAddress((void**)&p_chB,   g_chB);
    cudaGetSymbolAddress((void**)&p_hin,   g_hin);

    cudaFuncSetAttribute(gemm_bf16, cudaFuncAttributeMaxDynamicSharedMemorySize, GEMM_SMEM);

    dim3 blk(32, 8);

    rmsnorm_kernel<<<ROWS, 256>>>(x, ls, rs, ss, p_xn);
    prep_WT<<<dim3(2048/32, 1024/32, 4), blk>>>(Wk, Wugg, p_WT);
    transpose_bf16<<<dim3(1024/32, 2048/32), blk>>>(Wout, p_WoutT, 2048, 1024);
    // global launch index 5 -> ncu profiles GEMM1
    gemm_bf16<<<dim3(NTOT/128, ROWS/128), 128, GEMM_SMEM>>>(
        p_xn, p_WT, NTOT, DIMS, DIMS/BK, 0,
        p_CD, p_CU2, p_CGO, nullptr, nullptr);

    scan_phase1<<<dim3(STATE/256, NCH, BATCH), 256>>>(p_CD, p_CU2, p_chA, p_chB);
    scan_phase2<<<(BATCH*STATE)/256, 256>>>(p_chA, p_chB, p_hin);
    scan_phase3<<<dim3(STATE/256, NCH, BATCH), 256>>>(p_CD, p_CU2, p_CGO, p_hin, p_out1);

    gemm_bf16<<<dim3(DIMS/128, ROWS/128), 128, GEMM_SMEM>>>(
        p_out1, p_WoutT, DIMS, STATE, STATE/BK, 1,
        nullptr, nullptr, nullptr, y, x);
}

// round 14
// speedup vs baseline: 1.1501x; 1.0266x over previous
#include <cuda_runtime.h>
#include <cuda_bf16.h>
#include <math.h>
#include <stdint.h>

// ---------------- Problem constants ----------------
#define BATCH   4
#define SEQ     2048
#define ROWS    (BATCH*SEQ)      // 8192
#define DIMS    1024
#define STATE   2048             // 2*DIMS
#define NTOT    (4*STATE)        // 8192 logical GEMM1 columns [K | u/gin 8-blocked | gout]
#define TCH     128              // scan chunk length
#define NCH     (SEQ/TCH)        // 16 chunks

// ---------------- Scratch (device globals; no allocation allowed) ----------------
__device__ __nv_bfloat16 g_xn[(size_t)ROWS*DIMS];       // 16MB  normalized input (bf16)
__device__ __nv_bfloat16 g_WT[(size_t)NTOT*DIMS];       // 16MB  packed weights^T bf16
__device__ __nv_bfloat16 g_WoutT[(size_t)DIMS*STATE];   // 4MB   Wout^T as [n,k] bf16
__device__ __nv_bfloat16 g_CD [(size_t)ROWS*STATE];     // 32MB  d = 1-sig(K) bf16
__device__ __nv_bfloat16 g_CU2[(size_t)ROWS*STATE];     // 32MB  u2 = u*sig(gin) bf16
__device__ __nv_bfloat16 g_CGO[(size_t)ROWS*STATE];     // 32MB  sig(gout) bf16
__device__ __nv_bfloat16 g_out1[(size_t)ROWS*STATE];    // 32MB  h*sig(gout) bf16
__device__ float g_chA[BATCH*NCH*STATE];
__device__ float g_chB[BATCH*NCH*STATE];
__device__ float g_hin[BATCH*NCH*STATE];

// ---------------- Helpers ----------------
__device__ __forceinline__ uint32_t smem_u32(const void* p) {
    uint32_t a;
    asm("{ .reg .u64 t; cvta.to.shared.u64 t, %1; cvt.u32.u64 %0, t; }" : "=r"(a) : "l"(p));
    return a;
}
__device__ __forceinline__ void cp16(uint32_t dst, const void* src) {
    asm volatile("cp.async.cg.shared.global [%0], [%1], 16;" :: "r"(dst), "l"(src) : "memory");
}
#define CP_COMMIT() asm volatile("cp.async.commit_group;" ::: "memory")

__device__ __forceinline__ void ldm_x4(uint32_t* r, uint32_t addr) {
    asm volatile("ldmatrix.sync.aligned.m8n8.x4.shared.b16 {%0,%1,%2,%3}, [%4];"
                 : "=r"(r[0]), "=r"(r[1]), "=r"(r[2]), "=r"(r[3]) : "r"(addr));
}
__device__ __forceinline__ void mma_bf16(float* c, const uint32_t* a,
                                         uint32_t b0, uint32_t b1) {
    asm volatile(
        "mma.sync.aligned.m16n8k16.row.col.f32.bf16.bf16.f32 "
        "{%0,%1,%2,%3},{%4,%5,%6,%7},{%8,%9},{%0,%1,%2,%3};"
        : "+f"(c[0]), "+f"(c[1]), "+f"(c[2]), "+f"(c[3])
        : "r"(a[0]), "r"(a[1]), "r"(a[2]), "r"(a[3]), "r"(b0), "r"(b1));
}
// Fast sigmoid: MUFU.EX2-based exp + MUFU.RCP division (~4 SASS ops).
__device__ __forceinline__ float sigm(float v) {
    return __fdividef(1.0f, 1.0f + __expf(-v));
}

// ---------------- RMS split norm -> bf16 ----------------
__global__ void rmsnorm_kernel(const float* __restrict__ x,
                               const float* __restrict__ ls,
                               const float* __restrict__ rs,
                               const float* __restrict__ ss,
                               __nv_bfloat16* __restrict__ xn) {
    __shared__ float wsum[8];
    int row = blockIdx.x;
    int tid = threadIdx.x;                 // 256 threads, 4 elems each
    const float* xr = x + (size_t)row * DIMS;
    float4 xv = ((const float4*)xr)[tid];
    float s = xv.x*xv.x + xv.y*xv.y + xv.z*xv.z + xv.w*xv.w;
    #pragma unroll
    for (int o = 16; o; o >>= 1) s += __shfl_xor_sync(0xffffffffu, s, o);
    if ((tid & 31) == 0) wsum[tid >> 5] = s;
    __syncthreads();
    int half = tid >> 7;
    float tot = wsum[half*4+0] + wsum[half*4+1] + wsum[half*4+2] + wsum[half*4+3];
    float n = sqrtf(tot) * 0.04419417382415922f + 1e-8f;   // 1/sqrt(512)
    float inv = 1.0f / n;
    const float* sc = half ? rs : ls;
    int jb = (tid*4) & 511;
    float4 scv = ((const float4*)sc)[jb >> 2];
    float4 ssv = ((const float4*)ss)[tid];
    __nv_bfloat162 p0 = __floats2bfloat162_rn(xv.x * scv.x * inv * ssv.x,
                                              xv.y * scv.y * inv * ssv.y);
    __nv_bfloat162 p1 = __floats2bfloat162_rn(xv.z * scv.z * inv * ssv.z,
                                              xv.w * scv.w * inv * ssv.w);
    __nv_bfloat162* dst = (__nv_bfloat162*)(xn + (size_t)row * DIMS);
    dst[tid*2]   = p0;
    dst[tid*2+1] = p1;
}

// ---------------- Weight prep: u/gin interleave at 8-column granularity ----------------
// z=0: Wk col c         -> WT row c                              (d-plane logits)
// z=1: Wugg col c (u)   -> WT row 2048 + 16*(c>>3) + (c&7)       (u block)
// z=2: Wugg col 2048+c  -> WT row 2048 + 16*(c>>3) + 8 + (c&7)   (gin block)
// z=3: Wugg col 4096+c  -> WT row 6144 + c                       (gout)
__global__ void prep_WT(const float* __restrict__ Wk, const float* __restrict__ Wugg,
                        __nv_bfloat16* __restrict__ dst) {
    __shared__ float tile[32][33];
    int z = blockIdx.z;
    const float* src = (z == 0) ? Wk : (Wugg + (z - 1) * 2048);
    int srcLD = (z == 0) ? 2048 : 6144;
    int r0 = blockIdx.y * 32, c0 = blockIdx.x * 32;
    int tx = threadIdx.x, ty = threadIdx.y;   // 32 x 8
    #pragma unroll
    for (int i = 0; i < 32; i += 8)
        tile[ty+i][tx] = src[(size_t)(r0+ty+i)*srcLD + c0 + tx];
    __syncthreads();
    #pragma unroll
    for (int i = 0; i < 32; i += 8) {
        int c = c0 + ty + i;
        int dstRow;
        if      (z == 0) dstRow = c;
        else if (z == 1) dstRow = 2048 + 16*(c >> 3) + (c & 7);
        else if (z == 2) dstRow = 2048 + 16*(c >> 3) + 8 + (c & 7);
        else             dstRow = 6144 + c;
        dst[(size_t)dstRow*1024 + r0 + tx] = __float2bfloat16_rn(tile[tx][ty+i]);
    }
}

// ---------------- Plain transpose fp32 -> bf16 (Wout) ----------------
__global__ void transpose_bf16(const float* __restrict__ src, __nv_bfloat16* __restrict__ dst,
                               int R, int C) {
    __shared__ float tile[32][33];
    int r0 = blockIdx.y * 32, c0 = blockIdx.x * 32;
    int tx = threadIdx.x, ty = threadIdx.y;   // 32 x 8
    #pragma unroll
    for (int i = 0; i < 32; i += 8)
        tile[ty+i][tx] = src[(size_t)(r0+ty+i)*C + c0 + tx];
    __syncthreads();
    #pragma unroll
    for (int i = 0; i < 32; i += 8)
        dst[(size_t)(c0+ty+i)*R + r0 + tx] = __float2bfloat16_rn(tile[tx][ty+i]);
}

// ---------------- Legacy-MMA bf16 GEMM: CTA 128x128, 4 warps of 64x64, 2 CTA/SM ----------------
// R11/R12 mainloop (measured fast, frozen).
// mode 0: plane epilogue -> CD bf16 (d=sig(-K)), CU2 bf16 (u*sig(gin), paired nt regs),
//         CGO bf16 (sig(gout)); all bf16x2 coalesced stores.
// mode 1: y = acc + resid (fp32)
#define BK 64
#define NST 3
#define AST (128*BK*2)         // 16384 bytes per A stage
#define BST (128*BK*2)         // 16384 bytes per B stage
#define GEMM_SMEM (NST*(AST+BST))   // 98304 = 96KB

__global__ void __launch_bounds__(128, 2)
gemm_bf16(const __nv_bfloat16* __restrict__ A, const __nv_bfloat16* __restrict__ B,
          int N, int K, int NIT, int mode,
          __nv_bfloat16* __restrict__ pD, __nv_bfloat16* __restrict__ pU2,
          __nv_bfloat16* __restrict__ pGO,
          float* __restrict__ Cout, const float* __restrict__ resid) {
    extern __shared__ char smraw[];
    const uint32_t sbase = smem_u32(smraw);

    const int tid  = threadIdx.x;          // 0..127
    const int wid  = tid >> 5;             // 0..3
    const int lane = tid & 31;
    const int m0 = blockIdx.y * 128;
    const int n0 = blockIdx.x * 128;
    const int wm0 = (wid >> 1) * 64;       // warp row origin (0/64)
    const int wn0 = (wid & 1) * 64;        // warp col origin (0/64)
    const int blk = lane >> 3;             // 0..3
    const int lr8 = lane & 7;
    const int kb2 = (blk >> 1) * 16;       // +16B for k8..15 half

    // Hoisted fill addressing: 128 threads cover 16 rows/sweep, 8 sweeps per tile
    uint32_t sOff[8];
    uint32_t goA[8], goB[8];
    {
        int r = tid >> 3, c = tid & 7;
        #pragma unroll
        for (int i = 0; i < 8; i++) {
            int rr = r + i * 16;
            sOff[i] = (uint32_t)(rr * 128 + ((c ^ (rr & 7)) << 4));
            goA[i] = (uint32_t)((m0 + rr) * K + c * 8);
            goB[i] = (uint32_t)((n0 + rr) * K + c * 8);
        }
    }

    uint32_t offA[4], xrA[4], offB[4], xrB[4];
    #pragma unroll
    for (int mt = 0; mt < 4; mt++) {
        int r = wm0 + mt*16 + (blk & 1)*8 + lr8;
        offA[mt] = (uint32_t)r * 128u;
        xrA[mt]  = (uint32_t)(r & 7) << 4;
    }
    #pragma unroll
    for (int np = 0; np < 4; np++) {
        int r = wn0 + np*16 + (blk & 1)*8 + lr8;
        offB[np] = (uint32_t)r * 128u;
        xrB[np]  = (uint32_t)(r & 7) << 4;
    }

    float c[4][8][4];
    #pragma unroll
    for (int i = 0; i < 4; i++)
        #pragma unroll
        for (int j = 0; j < 8; j++)
            #pragma unroll
            for (int e = 0; e < 4; e++) c[i][j][e] = 0.0f;

    // Prologue: fill all 3 stages
    #pragma unroll
    for (int pf = 0; pf < NST; ++pf) {
        const uint32_t aS = sbase + pf*(AST+BST);
        const uint32_t bS = aS + AST;
        const uint32_t k0 = pf * BK;
        #pragma unroll
        for (int i = 0; i < 8; i++) cp16(aS + sOff[i], A + goA[i] + k0);
        #pragma unroll
        for (int i = 0; i < 8; i++) cp16(bS + sOff[i], B + goB[i] + k0);
        CP_COMMIT();
    }

    for (int it = 0; it < NIT; ++it) {
        const int s = it % NST;
        const uint32_t aS = sbase + s*(AST+BST);
        const uint32_t bS = aS + AST;

        int rem = NIT - 1 - it;
        if (rem >= 2)      asm volatile("cp.async.wait_group 2;" ::: "memory");
        else if (rem == 1) asm volatile("cp.async.wait_group 1;" ::: "memory");
        else               asm volatile("cp.async.wait_group 0;" ::: "memory");
        __syncthreads();

        #pragma unroll
        for (int kk = 0; kk < 4; ++kk) {
            uint32_t a[4][4], b[4][4];
            const uint32_t kbase = (uint32_t)(kk*32) + kb2;
            #pragma unroll
            for (int mt = 0; mt < 4; mt++)
                ldm_x4(a[mt], aS + offA[mt] + (kbase ^ xrA[mt]));
            #pragma unroll
            for (int np = 0; np < 4; np++)
                ldm_x4(b[np], bS + offB[np] + (kbase ^ xrB[np]));
            #pragma unroll
            for (int mt = 0; mt < 4; mt++)
                #pragma unroll
                for (int nt = 0; nt < 8; nt++) {
                    int np = nt >> 1, odd = nt & 1;
                    mma_bf16(c[mt][nt], a[mt], b[np][odd], b[np][2 + odd]);
                }
        }
        __syncthreads();   // everyone done reading stage s

        if (it + 3 < NIT) {
            const uint32_t k0 = (it + 3) * BK;
            #pragma unroll
            for (int i = 0; i < 8; i++) cp16(aS + sOff[i], A + goA[i] + k0);
            #pragma unroll
            for (int i = 0; i < 8; i++) cp16(bS + sOff[i], B + goB[i] + k0);
            CP_COMMIT();
        }
    }

    // Epilogue
    const int g = lane >> 2, tig = lane & 3;
    if (mode == 0) {
        if (n0 < 2048) {
            // d-plane: d = sig(-v), bf16x2 stores
            #pragma unroll
            for (int mt = 0; mt < 4; mt++) {
                int row = m0 + wm0 + mt*16 + g;
                #pragma unroll
                for (int nt = 0; nt < 8; nt++) {
                    int st = n0 + wn0 + nt*8 + 2*tig;
                    float d0 = sigm(-c[mt][nt][0]), d1 = sigm(-c[mt][nt][1]);
                    float d2 = sigm(-c[mt][nt][2]), d3 = sigm(-c[mt][nt][3]);
                    *(__nv_bfloat162*)(pD + (size_t)row * STATE + st)
                        = __floats2bfloat162_rn(d0, d1);
                    *(__nv_bfloat162*)(pD + (size_t)(row+8) * STATE + st)
                        = __floats2bfloat162_rn(d2, d3);
                }
            }
        } else if (n0 < 6144) {
            // u/gin plane (8-col blocks): nt even regs = u pair, nt odd regs = gin pair
            // for the SAME states; store u2 = u*sig(gin) as bf16x2.
            const int sbase0 = ((n0 - 2048) + wn0) >> 1;   // first state of this warp
            #pragma unroll
            for (int mt = 0; mt < 4; mt++) {
                int row = m0 + wm0 + mt*16 + g;
                #pragma unroll
                for (int j = 0; j < 4; j++) {
                    const int nte = 2*j, nto = 2*j + 1;
                    int st = sbase0 + j*8 + 2*tig;
                    float u20 = c[mt][nte][0] * sigm(c[mt][nto][0]);
                    float u21 = c[mt][nte][1] * sigm(c[mt][nto][1]);
                    float u22 = c[mt][nte][2] * sigm(c[mt][nto][2]);
                    float u23 = c[mt][nte][3] * sigm(c[mt][nto][3]);
                    *(__nv_bfloat162*)(pU2 + (size_t)row * STATE + st)
                        = __floats2bfloat162_rn(u20, u21);
                    *(__nv_bfloat162*)(pU2 + (size_t)(row+8) * STATE + st)
                        = __floats2bfloat162_rn(u22, u23);
                }
            }
        } else {
            #pragma unroll
            for (int mt = 0; mt < 4; mt++) {
                int row = m0 + wm0 + mt*16 + g;
                #pragma unroll
                for (int nt = 0; nt < 8; nt++) {
                    int st = (n0 - 6144) + wn0 + nt*8 + 2*tig;
                    float v0 = sigm(c[mt][nt][0]), v1 = sigm(c[mt][nt][1]);
                    float v2 = sigm(c[mt][nt][2]), v3 = sigm(c[mt][nt][3]);
                    *(__nv_bfloat162*)(pGO + (size_t)row * STATE + st)
                        = __floats2bfloat162_rn(v0, v1);
                    *(__nv_bfloat162*)(pGO + (size_t)(row+8) * STATE + st)
                        = __floats2bfloat162_rn(v2, v3);
                }
            }
        }
    } else {
        #pragma unroll
        for (int mt = 0; mt < 4; mt++) {
            int row = m0 + wm0 + mt*16 + g;
            #pragma unroll
            for (int nt = 0; nt < 8; nt++) {
                int col = n0 + wn0 + nt*8 + 2*tig;
                float v0 = c[mt][nt][0] + resid[(size_t)row * N + col];
                float v1 = c[mt][nt][1] + resid[(size_t)row * N + col + 1];
                float v2 = c[mt][nt][2] + resid[(size_t)(row+8) * N + col];
                float v3 = c[mt][nt][3] + resid[(size_t)(row+8) * N + col + 1];
                *(float2*)(Cout + (size_t)row * N + col)     = make_float2(v0, v1);
                *(float2*)(Cout + (size_t)(row+8) * N + col) = make_float2(v2, v3);
            }
        }
    }
}

// ---------------- Chunked linear-recurrence scan (d, u2, gout all bf16) ----------------
// a_t = 1 - d_{t-1}; u'_t = u2_t * d_t; h_t = a_t h_{t-1} + u'_t
__global__ void scan_phase1(const __nv_bfloat16* __restrict__ CD,
                            const __nv_bfloat16* __restrict__ CU2,
                            float* __restrict__ chA, float* __restrict__ chB) {
    int cidx  = blockIdx.x * blockDim.x + threadIdx.x;   // 0..2047
    int chunk = blockIdx.y;
    int b     = blockIdx.z;
    float Aacc = 1.0f, Bacc = 0.0f;
    int t0 = chunk * TCH;
    size_t row0 = (size_t)b * SEQ + t0;
    float dprev = (t0 == 0) ? 0.0f : __bfloat162float(CD[(row0 - 1) * STATE + cidx]);
    for (int tl = 0; tl < TCH; tl++) {
        size_t r = (row0 + tl) * STATE + cidx;
        float d  = __bfloat162float(CD[r]);
        float u2 = __bfloat162float(CU2[r]);
        float a  = 1.0f - dprev;
        dprev = d;
        float up = u2 * d;
        Aacc = a * Aacc;
        Bacc = a * Bacc + up;
    }
    int idx = (b * NCH + chunk) * STATE + cidx;
    chA[idx] = Aacc;
    chB[idx] = Bacc;
}

__global__ void scan_phase2(const float* __restrict__ chA,
                            const float* __restrict__ chB,
                            float* __restrict__ hin) {
    int i = blockIdx.x * blockDim.x + threadIdx.x;   // b*2048+c
    int b = i >> 11, cidx = i & 2047;
    float h = 0.0f;
    for (int ch = 0; ch < NCH; ch++) {
        int idx = (b * NCH + ch) * STATE + cidx;
        hin[idx] = h;
        h = chA[idx] * h + chB[idx];
    }
}

__global__ void scan_phase3(const __nv_bfloat16* __restrict__ CD,
                            const __nv_bfloat16* __restrict__ CU2,
                            const __nv_bfloat16* __restrict__ CGO,
                            const float* __restrict__ hin,
                            __nv_bfloat16* __restrict__ out1) {
    int cidx  = blockIdx.x * blockDim.x + threadIdx.x;
    int chunk = blockIdx.y;
    int b     = blockIdx.z;
    float h = hin[(b * NCH + chunk) * STATE + cidx];
    int t0 = chunk * TCH;
    size_t row0 = (size_t)b * SEQ + t0;
    float dprev = (t0 == 0) ? 0.0f : __bfloat162float(CD[(row0 - 1) * STATE + cidx]);
    for (int tl = 0; tl < TCH; tl++) {
        size_t r = (row0 + tl) * STATE + cidx;
        float d  = __bfloat162float(CD[r]);
        float u2 = __bfloat162float(CU2[r]);
        float go = __bfloat162float(CGO[r]);
        float a  = 1.0f - dprev;
        dprev = d;
        h = a * h + u2 * d;
        out1[r] = __float2bfloat16_rn(h * go);
    }
}

// ---------------- Launch ----------------
extern "C" void kernel_launch(void* const* d_in, const int* in_sizes, int n_in,
                              void* d_out, int out_size) {
    const float* x    = (const float*)d_in[0];
    const float* ls   = (const float*)d_in[1];
    const float* rs   = (const float*)d_in[2];
    const float* ss   = (const float*)d_in[3];
    const float* Wk   = (const float*)d_in[4];
    const float* Wugg = (const float*)d_in[5];
    const float* Wout = (const float*)d_in[6];
    float* y = (float*)d_out;

    __nv_bfloat16 *p_xn, *p_WT, *p_WoutT, *p_out1, *p_CD, *p_CU2, *p_CGO;
    float *p_chA, *p_chB, *p_hin;
    cudaGetSymbolAddress((void**)&p_xn,    g_xn);
    cudaGetSymbolAddress((void**)&p_WT,    g_WT);
    cudaGetSymbolAddress((void**)&p_WoutT, g_WoutT);
    cudaGetSymbolAddress((void**)&p_CD,    g_CD);
    cudaGetSymbolAddress((void**)&p_CU2,   g_CU2);
    cudaGetSymbolAddress((void**)&p_CGO,   g_CGO);
    cudaGetSymbolAddress((void**)&p_out1,  g_out1);
    cudaGetSymbolAddress((void**)&p_chA,   g_chA);
    cudaGetSymbolAddress((void**)&p_chB,   g_chB);
    cudaGetSymbolAddress((void**)&p_hin,   g_hin);

    cudaFuncSetAttribute(gemm_bf16, cudaFuncAttributeMaxDynamicSharedMemorySize, GEMM_SMEM);

    dim3 blk(32, 8);

    rmsnorm_kernel<<<ROWS, 256>>>(x, ls, rs, ss, p_xn);
    prep_WT<<<dim3(2048/32, 1024/32, 4), blk>>>(Wk, Wugg, p_WT);
    transpose_bf16<<<dim3(1024/32, 2048/32), blk>>>(Wout, p_WoutT, 2048, 1024);
    // global launch index 5 -> ncu profiles GEMM1
    gemm_bf16<<<dim3(NTOT/128, ROWS/128), 128, GEMM_SMEM>>>(
        p_xn, p_WT, NTOT, DIMS, DIMS/BK, 0,
        p_CD, p_CU2, p_CGO, nullptr, nullptr);

    scan_phase1<<<dim3(STATE/256, NCH, BATCH), 256>>>(p_CD, p_CU2, p_chA, p_chB);
    scan_phase2<<<(BATCH*STATE)/256, 256>>>(p_chA, p_chB, p_hin);
    scan_phase3<<<dim3(STATE/256, NCH, BATCH), 256>>>(p_CD, p_CU2, p_CGO, p_hin, p_out1);

    gemm_bf16<<<dim3(DIMS/128, ROWS/128), 128, GEMM_SMEM>>>(
        p_out1, p_WoutT, DIMS, STATE, STATE/BK, 1,
        nullptr, nullptr, nullptr, y, x);
}